// round 1
// baseline (speedup 1.0000x reference)
#include <cuda_runtime.h>
#include <cuda_fp16.h>
#include <math.h>

#define BB 16
#define C  128
#define F  128
#define HH 128
#define WW 128
#define KHH 31
#define KWW 31
#define OH 98
#define OW 98
#define NF 65          // rfft bins along W
#define NBIN (HH*NF)   // 8320
#define BC (BB*C)      // 2048
#define FC (F*C)       // 16384

// -------- scratch (device globals; no allocation allowed) --------
__device__ float2  g_xf [(size_t)BC  * NBIN];   // [b*C+c][bin]   136 MB fp32 complex
__device__ __half2 g_kfn[(size_t)FC  * NBIN];   // [f*C+c][bin]   545 MB fp16 complex (conj)
__device__ __half2 g_kft[(size_t)NBIN * FC];    // [bin][f*C+c]   545 MB (transposed)
__device__ float2  g_of [(size_t)NBIN * BC];    // [bin][b*F+f]   136 MB

// ---------------- batched 128-pt Stockham FFT in smem ----------------
// tw[k] = exp(-2*pi*i*k/128), k=0..63.  rows independent FFTs, row stride 128.
// Ping-pongs A<->B each stage (7 stages); returns buffer holding the result.
__device__ __forceinline__ float2* fft128(float2* A, float2* B, int rows,
                                          const float2* tw, int tid, int nth) {
    #pragma unroll
    for (int s = 0; s < 7; s++) {
        int m = 1 << s;
        int total = rows << 6;                 // rows * 64 butterflies
        for (int idx = tid; idx < total; idx += nth) {
            int r  = idx >> 6;
            int t  = idx & 63;
            int lo = t & (m - 1);
            int hi = t ^ lo;                   // j*m
            int base = r << 7;
            float2 a0 = A[base + t];
            float2 a1 = A[base + t + 64];
            float2 w  = tw[hi];
            float2 su = make_float2(a0.x + a1.x, a0.y + a1.y);
            float2 di = make_float2(a0.x - a1.x, a0.y - a1.y);
            float2 dm = make_float2(di.x * w.x - di.y * w.y,
                                    di.x * w.y + di.y * w.x);
            B[base + 2 * hi + lo]     = su;
            B[base + 2 * hi + lo + m] = dm;
        }
        __syncthreads();
        float2* tmp = A; A = B; B = tmp;
    }
    return A;
}

__device__ __forceinline__ void make_twiddles(float2* tw, int tid) {
    if (tid < 64) {
        float s, c;
        sincosf(-6.283185307179586f * (float)tid / 128.0f, &s, &c);
        tw[tid] = make_float2(c, s);
    }
}

// ---------------- K1: 2D rFFT of x -> g_xf[bc][bin] ----------------
__global__ void __launch_bounds__(256) k_fft_x(const float* __restrict__ x) {
    extern __shared__ float2 sm[];
    float2* tw = sm;            // 64
    float2* bufA = sm + 64;     // NBIN
    float2* bufB = bufA + NBIN; // NBIN
    int tid = threadIdx.x, nth = blockDim.x;
    int bc = blockIdx.x;        // b*C + c

    make_twiddles(tw, tid);
    const float* img = x + (size_t)bc * HH * WW;
    // pack row pairs: z[r][n] = x[2r][n] + i x[2r+1][n]
    for (int idx = tid; idx < 64 * 128; idx += nth) {
        int r = idx >> 7, n = idx & 127;
        bufA[(r << 7) + n] = make_float2(img[(2 * r) * WW + n],
                                         img[(2 * r + 1) * WW + n]);
    }
    __syncthreads();
    float2* P = fft128(bufA, bufB, 64, tw, tid, nth);
    float2* S = (P == bufA) ? bufB : bufA;
    // unpack into spectrum S[k][h], k=0..64, h=0..127
    for (int idx = tid; idx < 64 * NF; idx += nth) {
        int r = idx / NF, k = idx - r * NF;
        float2 Zk = P[(r << 7) + k];
        float2 Zn = P[(r << 7) + ((128 - k) & 127)];
        float2 Ar = make_float2(0.5f * (Zk.x + Zn.x), 0.5f * (Zk.y - Zn.y));
        float2 Br = make_float2(0.5f * (Zk.y + Zn.y), 0.5f * (Zn.x - Zk.x));
        S[(k << 7) + 2 * r]     = Ar;
        S[(k << 7) + 2 * r + 1] = Br;
    }
    __syncthreads();
    float2* Sc = (S == bufA) ? bufB : bufA;
    float2* Ff = fft128(S, Sc, NF, tw, tid, nth);
    // store coalesced: bin = h*NF + k
    float2* ob = g_xf + (size_t)bc * NBIN;
    for (int bin = tid; bin < NBIN; bin += nth) {
        int h = bin / NF, k = bin - h * NF;
        ob[bin] = Ff[(k << 7) + h];
    }
}

// ---------------- K2: 2D rFFT of filters (conj) -> g_kfn[fc][bin] fp16 ----------------
__global__ void __launch_bounds__(256) k_fft_k(const float* __restrict__ filt) {
    extern __shared__ float2 sm[];
    float2* tw = sm;
    float2* bufA = sm + 64;
    float2* bufB = bufA + NBIN;
    int tid = threadIdx.x, nth = blockDim.x;
    int fc = blockIdx.x;        // f*C + c

    make_twiddles(tw, tid);
    // zero the 16 packed rows (covers filter rows 0..31)
    for (int idx = tid; idx < 16 * 128; idx += nth)
        bufA[idx] = make_float2(0.f, 0.f);
    __syncthreads();
    const float* kimg = filt + (size_t)fc * KHH * KWW;
    for (int idx = tid; idx < KHH * KWW; idx += nth) {
        int i = idx / KWW, j = idx - i * KWW;
        float v = kimg[idx];
        int r = i >> 1;
        if (i & 1) bufA[(r << 7) + j].y = v;
        else       bufA[(r << 7) + j].x = v;
    }
    __syncthreads();
    float2* P = fft128(bufA, bufB, 16, tw, tid, nth);
    float2* S = (P == bufA) ? bufB : bufA;
    // zero full spectrum then fill h=0..31
    for (int idx = tid; idx < NF * 128; idx += nth)
        S[idx] = make_float2(0.f, 0.f);
    __syncthreads();
    for (int idx = tid; idx < 16 * NF; idx += nth) {
        int r = idx / NF, k = idx - r * NF;
        float2 Zk = P[(r << 7) + k];
        float2 Zn = P[(r << 7) + ((128 - k) & 127)];
        float2 Ar = make_float2(0.5f * (Zk.x + Zn.x), 0.5f * (Zk.y - Zn.y));
        float2 Br = make_float2(0.5f * (Zk.y + Zn.y), 0.5f * (Zn.x - Zk.x));
        S[(k << 7) + 2 * r]     = Ar;
        S[(k << 7) + 2 * r + 1] = Br;
    }
    __syncthreads();
    float2* Sc = (S == bufA) ? bufB : bufA;
    float2* Ff = fft128(S, Sc, NF, tw, tid, nth);
    // store conj(kf) as fp16 complex, coalesced
    __half2* ob = g_kfn + (size_t)fc * NBIN;
    for (int bin = tid; bin < NBIN; bin += nth) {
        int h = bin / NF, k = bin - h * NF;
        float2 v = Ff[(k << 7) + h];
        ob[bin] = __floats2half2_rn(v.x, -v.y);   // low = re, high = -im (conj)
    }
}

// ---------------- K3: transpose kf [fc][bin] -> [bin][fc] (4B elems) ----------------
__global__ void __launch_bounds__(256) k_transpose() {
    __shared__ unsigned int t[32][33];
    const unsigned int* src = (const unsigned int*)g_kfn;
    unsigned int* dst = (unsigned int*)g_kft;
    int x0 = blockIdx.x * 32;   // bin  (8320/32 = 260)
    int y0 = blockIdx.y * 32;   // fc   (16384/32 = 512)
    for (int i = threadIdx.y; i < 32; i += 8)
        t[i][threadIdx.x] = src[(size_t)(y0 + i) * NBIN + x0 + threadIdx.x];
    __syncthreads();
    for (int i = threadIdx.y; i < 32; i += 8)
        dst[(size_t)(x0 + i) * FC + y0 + threadIdx.x] = t[threadIdx.x][i];
}

// ---------------- K4: per-bin complex GEMM of = X * conj(K)^T ----------------
// X: [16 x 128] fp32 complex (smem, duplicated for f32x2), K: [128 x 128] fp16 complex.
#define KS_STRIDE 129   // pad to avoid 32-way LDS bank conflict
__global__ void __launch_bounds__(128) k_gemm() {
    extern __shared__ char smraw[];
    float2*  xr = (float2*)smraw;          // (Xr,Xr)  2048
    float2*  xi = xr + BC;                 // (Xi,Xi)  2048
    __half2* ks = (__half2*)(xi + BC);     // 128 x KS_STRIDE
    int bin = blockIdx.x;
    int tid = threadIdx.x;                 // = f

    for (int i = tid; i < BC; i += 128) {
        float2 v = g_xf[(size_t)i * NBIN + bin];   // strided; L2-amortized across bins
        xr[i] = make_float2(v.x, v.x);
        xi[i] = make_float2(v.y, v.y);
    }
    const __half2* ksrc = g_kft + (size_t)bin * FC;
    for (int i = tid; i < FC; i += 128) {
        int f = i >> 7, c = i & 127;
        ks[f * KS_STRIDE + c] = ksrc[i];
    }
    __syncthreads();

    unsigned long long acc[BB];
    #pragma unroll
    for (int b = 0; b < BB; b++) acc[b] = 0ULL;

    const __half2* krow = ks + tid * KS_STRIDE;
    #pragma unroll 2
    for (int c = 0; c < C; c++) {
        float2 kv = __half22float2(krow[c]);     // (kr, ki) with ki = -im(fft)
        unsigned long long K1, K2;
        float nky = -kv.y;
        asm("mov.b64 %0, {%1,%2};" : "=l"(K1) : "f"(kv.x), "f"(kv.y));
        asm("mov.b64 %0, {%1,%2};" : "=l"(K2) : "f"(nky),  "f"(kv.x));
        #pragma unroll
        for (int b = 0; b < BB; b++) {
            unsigned long long xrv = *(const unsigned long long*)&xr[b * C + c];
            unsigned long long xiv = *(const unsigned long long*)&xi[b * C + c];
            asm("fma.rn.f32x2 %0, %1, %2, %0;" : "+l"(acc[b]) : "l"(xrv), "l"(K1));
            asm("fma.rn.f32x2 %0, %1, %2, %0;" : "+l"(acc[b]) : "l"(xiv), "l"(K2));
        }
    }
    float2* ob = g_of + (size_t)bin * BC;
    #pragma unroll
    for (int b = 0; b < BB; b++) {
        float2 v;
        asm("mov.b64 {%0,%1}, %2;" : "=f"(v.x), "=f"(v.y) : "l"(acc[b]));
        ob[b * F + tid] = v;
    }
}

// ---------------- K5: 2D irFFT + slice + bias ----------------
__global__ void __launch_bounds__(256) k_ifft(float* __restrict__ out,
                                              const float* __restrict__ bias) {
    extern __shared__ float2 sm[];
    float2* tw = sm;
    float2* bufA = sm + 64;
    float2* bufB = bufA + NBIN;
    int tid = threadIdx.x, nth = blockDim.x;
    int bf = blockIdx.x;        // b*F + f
    int f  = bf & 127;

    make_twiddles(tw, tid);
    // load conj(of) arranged [k][h_freq]
    for (int bin = tid; bin < NBIN; bin += nth) {
        float2 v = g_of[(size_t)bin * BC + bf];
        int h = bin / NF, k = bin - h * NF;
        bufA[(k << 7) + h] = make_float2(v.x, -v.y);
    }
    __syncthreads();
    // column inverse (unnormalized): R = FFT(conj) ; Cinv = conj(R)
    float2* R = fft128(bufA, bufB, NF, tw, tid, nth);
    float2* T = (R == bufA) ? bufB : bufA;
    // build conj(Z_r[k]) for packed inverse rfft along W (row pairs 2r,2r+1)
    for (int idx = tid; idx < 64 * 128; idx += nth) {
        int r = idx >> 7, k = idx & 127;
        float2 val;
        if (k <= 64) {
            float2 a = R[(k << 7) + 2 * r];
            float2 b = R[(k << 7) + 2 * r + 1];
            val = make_float2(a.x + b.y, a.y - b.x);
        } else {
            int kk = 128 - k;
            float2 a = R[(kk << 7) + 2 * r];
            float2 b = R[(kk << 7) + 2 * r + 1];
            val = make_float2(a.x - b.y, -a.y - b.x);
        }
        T[(r << 7) + k] = val;
    }
    __syncthreads();
    float2* Tc = (T == bufA) ? bufB : bufA;
    float2* Y = fft128(T, Tc, 64, tw, tid, nth);
    // z = conj(Y)/16384 : even spatial row -> Y.x, odd -> -Y.y
    const float inv = 1.0f / 16384.0f;
    float bv = bias[f];
    float* ob = out + (size_t)bf * OH * OW;
    for (int idx = tid; idx < OH * OW; idx += nth) {
        int oh = idx / OW, ow = idx - oh * OW;
        float2 y = Y[((oh >> 1) << 7) + ow];
        float v = (oh & 1) ? -y.y : y.x;
        ob[idx] = v * inv + bv;
    }
}

// ---------------- launch ----------------
extern "C" void kernel_launch(void* const* d_in, const int* in_sizes, int n_in,
                              void* d_out, int out_size) {
    const float* x    = (const float*)d_in[0];
    const float* filt = (const float*)d_in[1];
    const float* bias = (const float*)d_in[2];
    float* out = (float*)d_out;

    int smFFT  = (64 + 2 * NBIN) * (int)sizeof(float2);                 // 133,632 B
    int smGEMM = 2 * BC * (int)sizeof(float2) + F * KS_STRIDE * 4;      // 98,816 B
    cudaFuncSetAttribute(k_fft_x,  cudaFuncAttributeMaxDynamicSharedMemorySize, smFFT);
    cudaFuncSetAttribute(k_fft_k,  cudaFuncAttributeMaxDynamicSharedMemorySize, smFFT);
    cudaFuncSetAttribute(k_ifft,   cudaFuncAttributeMaxDynamicSharedMemorySize, smFFT);
    cudaFuncSetAttribute(k_gemm,   cudaFuncAttributeMaxDynamicSharedMemorySize, smGEMM);

    k_fft_x<<<BC, 256, smFFT>>>(x);
    k_fft_k<<<FC, 256, smFFT>>>(filt);
    k_transpose<<<dim3(NBIN / 32, FC / 32), dim3(32, 8)>>>();
    k_gemm<<<NBIN, 128, smGEMM>>>();
    k_ifft<<<BC, 256, smFFT>>>(out, bias);
}

// round 2
// speedup vs baseline: 1.2531x; 1.2531x over previous
#include <cuda_runtime.h>
#include <cuda_fp16.h>
#include <math.h>

#define BB 16
#define C  128
#define F  128
#define HH 128
#define WW 128
#define KHH 31
#define KWW 31
#define OH 98
#define OW 98
#define NF 65          // rfft bins along W
#define NBIN (HH*NF)   // 8320
#define BC (BB*C)      // 2048
#define FC (F*C)       // 16384

// -------- scratch (device globals; no allocation allowed) --------
__device__ float2  g_xf [(size_t)BC  * NBIN];   // [b*C+c][bin]
__device__ __half2 g_kfn[(size_t)FC  * NBIN];   // [c*F+f][bin]  (conj, fp16)
__device__ __half2 g_kft[(size_t)NBIN * FC];    // [bin][c*F+f]
__device__ float2  g_of [(size_t)NBIN * BC];    // [bin][b*F+f]

// ---------------- helpers ----------------
__device__ __forceinline__ int swz(int w) { return w ^ ((w >> 4) & 7); }
__device__ __forceinline__ float2 cadd(float2 a, float2 b){return make_float2(a.x+b.x, a.y+b.y);}
__device__ __forceinline__ float2 csub(float2 a, float2 b){return make_float2(a.x-b.x, a.y-b.y);}
__device__ __forceinline__ float2 cmul(float2 a, float2 b){return make_float2(a.x*b.x-a.y*b.y, a.x*b.y+a.y*b.x);}
__device__ __forceinline__ float2 cmulni(float2 a){return make_float2(a.y, -a.x);}  // a * (-i)

__device__ __forceinline__ void make_twiddles(float2* tw, int tid) {
    if (tid < 128) {
        float s, c;
        sincosf(-6.283185307179586f * (float)tid / 128.0f, &s, &c);
        tw[tid] = make_float2(c, s);
    }
}

// DFT8 natural order: c[k] = sum_j a[j] W8^{jk}
__device__ __forceinline__ void dft8(const float2* a, float2* c) {
    float2 t0 = cadd(a[0], a[4]), t1 = csub(a[0], a[4]);
    float2 t2 = cadd(a[2], a[6]), t3 = csub(a[2], a[6]);
    float2 m3 = cmulni(t3);
    float2 E0 = cadd(t0, t2), E2 = csub(t0, t2);
    float2 E1 = cadd(t1, m3), E3 = csub(t1, m3);
    t0 = cadd(a[1], a[5]); t1 = csub(a[1], a[5]);
    t2 = cadd(a[3], a[7]); t3 = csub(a[3], a[7]);
    m3 = cmulni(t3);
    float2 O0 = cadd(t0, t2), O2 = csub(t0, t2);
    float2 O1 = cadd(t1, m3), O3 = csub(t1, m3);
    const float s = 0.70710678118654752f;
    float2 w1o = make_float2(s * (O1.x + O1.y), s * (O1.y - O1.x));
    float2 w2o = cmulni(O2);
    float2 w3o = make_float2(s * (O3.y - O3.x), s * (-O3.x - O3.y));
    c[0] = cadd(E0, O0);  c[4] = csub(E0, O0);
    c[1] = cadd(E1, w1o); c[5] = csub(E1, w1o);
    c[2] = cadd(E2, w2o); c[6] = csub(E2, w2o);
    c[3] = cadd(E3, w3o); c[7] = csub(E3, w3o);
}

// Stockham radix-8 pass, N=128.  B[8*hi+lo+k*M] = W128^{hi*k} * DFT8(a)[k]
template<int M>
__device__ __forceinline__ void pass8(const float2* __restrict__ A, float2* __restrict__ B,
                                      int rows, const float2* __restrict__ tw, int tid, int nth) {
    int total = rows << 4;
    for (int idx = tid; idx < total; idx += nth) {
        int r = idx >> 4, t = idx & 15;
        int lo = t & (M - 1), hi = t - lo;
        int base = r << 7;
        float2 a[8], c[8];
        #pragma unroll
        for (int j = 0; j < 8; j++) a[j] = A[base + swz(t + 16 * j)];
        dft8(a, c);
        int p = 8 * hi + lo;
        B[base + swz(p)] = c[0];
        #pragma unroll
        for (int k = 1; k < 8; k++)
            B[base + swz(p + k * M)] = cmul(c[k], tw[(hi * k) & 127]);
    }
}

// sparse radix-8 first pass (M=1): only inputs 0..31 nonzero (j=0,1)
__device__ __forceinline__ void pass8_sp2(const float2* __restrict__ A, float2* __restrict__ B,
                                          int rows, const float2* __restrict__ tw, int tid, int nth) {
    int total = rows << 4;
    for (int idx = tid; idx < total; idx += nth) {
        int r = idx >> 4, t = idx & 15;
        int base = r << 7;
        float2 a0 = A[base + swz(t)];
        float2 a1 = A[base + swz(t + 16)];
        #pragma unroll
        for (int k = 0; k < 8; k++) {
            float2 ck = cadd(a0, cmul(a1, tw[(16 * k) & 127]));
            B[base + swz(8 * t + k)] = cmul(ck, tw[(t * k) & 127]);
        }
    }
}

// final radix-2 pass (M=64), hi==0 so no twiddle
__device__ __forceinline__ void pass2f(const float2* __restrict__ A, float2* __restrict__ B,
                                       int rows, int tid, int nth) {
    int total = rows << 6;
    for (int idx = tid; idx < total; idx += nth) {
        int r = idx >> 6, t = idx & 63;
        int base = r << 7;
        float2 a0 = A[base + swz(t)];
        float2 a1 = A[base + swz(t + 64)];
        B[base + swz(t)]      = cadd(a0, a1);
        B[base + swz(t + 64)] = csub(a0, a1);
    }
}

// full 128-pt FFT over `rows` rows; input in A (swizzled), result in B (swizzled)
__device__ __forceinline__ float2* fft128_r8(float2* A, float2* B, int rows,
                                             const float2* tw, int tid, int nth) {
    pass8<1>(A, B, rows, tw, tid, nth); __syncthreads();
    pass8<8>(B, A, rows, tw, tid, nth); __syncthreads();
    pass2f(A, B, rows, tid, nth);       __syncthreads();
    return B;
}

// ---------------- K1: 2D rFFT of x -> g_xf[bc][bin] ----------------
__global__ void __launch_bounds__(512) k_fft_x(const float* __restrict__ x) {
    extern __shared__ float2 sm[];
    float2* tw = sm;             // 128
    float2* bufA = sm + 128;
    float2* bufB = bufA + NBIN;
    int tid = threadIdx.x, nth = blockDim.x;
    int bc = blockIdx.x;

    make_twiddles(tw, tid);
    const float* img = x + (size_t)bc * HH * WW;
    for (int idx = tid; idx < 64 * 128; idx += nth) {
        int r = idx >> 7, n = idx & 127;
        bufA[(r << 7) + swz(n)] = make_float2(img[(2 * r) * WW + n],
                                              img[(2 * r + 1) * WW + n]);
    }
    __syncthreads();
    float2* P = fft128_r8(bufA, bufB, 64, tw, tid, nth);    // bufB
    float2* S = bufA;
    for (int idx = tid; idx < 64 * NF; idx += nth) {
        int r = idx / NF, k = idx - r * NF;
        float2 Zk = P[(r << 7) + swz(k)];
        float2 Zn = P[(r << 7) + swz((128 - k) & 127)];
        float2 Ar = make_float2(0.5f * (Zk.x + Zn.x), 0.5f * (Zk.y - Zn.y));
        float2 Br = make_float2(0.5f * (Zk.y + Zn.y), 0.5f * (Zn.x - Zk.x));
        S[(k << 7) + swz(2 * r)]     = Ar;
        S[(k << 7) + swz(2 * r + 1)] = Br;
    }
    __syncthreads();
    float2* Ff = fft128_r8(bufA, bufB, NF, tw, tid, nth);   // bufB
    float2* ob = g_xf + (size_t)bc * NBIN;
    for (int bin = tid; bin < NBIN; bin += nth) {
        int h = bin / NF, k = bin - h * NF;
        ob[bin] = Ff[(k << 7) + swz(h)];
    }
}

// ---------------- K2: 2D rFFT of filters (conj, fp16) -> g_kfn[c*F+f][bin] ----------------
__global__ void __launch_bounds__(512) k_fft_k(const float* __restrict__ filt) {
    extern __shared__ float2 sm[];
    float2* tw = sm;
    float2* bufA = sm + 128;
    float2* bufB = bufA + NBIN;
    int tid = threadIdx.x, nth = blockDim.x;
    int fc = blockIdx.x;
    int f = fc >> 7, c = fc & 127;

    make_twiddles(tw, tid);
    for (int idx = tid; idx < 16 * 128; idx += nth)
        bufA[idx] = make_float2(0.f, 0.f);
    __syncthreads();
    const float* kimg = filt + (size_t)fc * KHH * KWW;
    for (int idx = tid; idx < KHH * KWW; idx += nth) {
        int i = idx / KWW, j = idx - i * KWW;
        float v = kimg[idx];
        int r = i >> 1;
        if (i & 1) bufA[(r << 7) + swz(j)].y = v;
        else       bufA[(r << 7) + swz(j)].x = v;
    }
    __syncthreads();
    float2* P = fft128_r8(bufA, bufB, 16, tw, tid, nth);    // bufB
    float2* S = bufA;
    for (int idx = tid; idx < 16 * NF; idx += nth) {
        int r = idx / NF, k = idx - r * NF;
        float2 Zk = P[(r << 7) + swz(k)];
        float2 Zn = P[(r << 7) + swz((128 - k) & 127)];
        float2 Ar = make_float2(0.5f * (Zk.x + Zn.x), 0.5f * (Zk.y - Zn.y));
        float2 Br = make_float2(0.5f * (Zk.y + Zn.y), 0.5f * (Zn.x - Zk.x));
        S[(k << 7) + swz(2 * r)]     = Ar;
        S[(k << 7) + swz(2 * r + 1)] = Br;
    }
    __syncthreads();
    // column FFT: only h<32 nonzero -> sparse first pass
    pass8_sp2(bufA, bufB, NF, tw, tid, nth); __syncthreads();
    pass8<8>(bufB, bufA, NF, tw, tid, nth);  __syncthreads();
    pass2f(bufA, bufB, NF, tid, nth);        __syncthreads();
    float2* Ff = bufB;
    __half2* ob = g_kfn + (size_t)(c * F + f) * NBIN;
    for (int bin = tid; bin < NBIN; bin += nth) {
        int h = bin / NF, k = bin - h * NF;
        float2 v = Ff[(k << 7) + swz(h)];
        ob[bin] = __floats2half2_rn(v.x, -v.y);
    }
}

// ---------------- K3: transpose kf [cf][bin] -> [bin][cf] ----------------
__global__ void __launch_bounds__(256) k_transpose() {
    __shared__ unsigned int t[32][33];
    const unsigned int* src = (const unsigned int*)g_kfn;
    unsigned int* dst = (unsigned int*)g_kft;
    int x0 = blockIdx.x * 32;   // bin
    int y0 = blockIdx.y * 32;   // cf
    for (int i = threadIdx.y; i < 32; i += 8)
        t[i][threadIdx.x] = src[(size_t)(y0 + i) * NBIN + x0 + threadIdx.x];
    __syncthreads();
    for (int i = threadIdx.y; i < 32; i += 8)
        dst[(size_t)(x0 + i) * FC + y0 + threadIdx.x] = t[threadIdx.x][i];
}

// ---------------- K4: per-bin complex GEMM of = X * conj(K)^T ----------------
// thread tile: 4 batches x 4 f's.  ks smem layout [c][f] (no transpose needed).
__global__ void __launch_bounds__(128, 2) k_gemm() {
    extern __shared__ char smraw[];
    float2*  xr = (float2*)smraw;          // (Xr,Xr) pairs, [b*C+c]
    float2*  xi = xr + BC;
    __half2* ks = (__half2*)(xi + BC);     // [c][f]
    int bin = blockIdx.x;
    int tid = threadIdx.x;
    int fg = tid & 31;          // f base lane; f = fg + 32j
    int b0 = (tid >> 5) << 2;   // 4 batches

    for (int i = tid; i < BC; i += 128) {
        float2 v = g_xf[(size_t)i * NBIN + bin];
        xr[i] = make_float2(v.x, v.x);
        xi[i] = make_float2(v.y, v.y);
    }
    const __half2* ksrc = g_kft + (size_t)bin * FC;  // [c*F+f]
    for (int i = tid; i < FC; i += 128)
        ks[i] = ksrc[i];
    __syncthreads();

    unsigned long long acc[16];
    #pragma unroll
    for (int i = 0; i < 16; i++) acc[i] = 0ULL;

    #pragma unroll 2
    for (int c = 0; c < C; c++) {
        unsigned long long xrv[4], xiv[4];
        #pragma unroll
        for (int i = 0; i < 4; i++) {
            xrv[i] = *(const unsigned long long*)&xr[(b0 + i) * C + c];
            xiv[i] = *(const unsigned long long*)&xi[(b0 + i) * C + c];
        }
        #pragma unroll
        for (int j = 0; j < 4; j++) {
            float2 kv = __half22float2(ks[(c << 7) + fg + (j << 5)]);
            unsigned long long K1, K2;
            float nky = -kv.y;
            asm("mov.b64 %0, {%1,%2};" : "=l"(K1) : "f"(kv.x), "f"(kv.y));
            asm("mov.b64 %0, {%1,%2};" : "=l"(K2) : "f"(nky),  "f"(kv.x));
            #pragma unroll
            for (int i = 0; i < 4; i++) {
                asm("fma.rn.f32x2 %0, %1, %2, %0;" : "+l"(acc[i * 4 + j]) : "l"(xrv[i]), "l"(K1));
                asm("fma.rn.f32x2 %0, %1, %2, %0;" : "+l"(acc[i * 4 + j]) : "l"(xiv[i]), "l"(K2));
            }
        }
    }
    float2* ob = g_of + (size_t)bin * BC;
    #pragma unroll
    for (int i = 0; i < 4; i++) {
        #pragma unroll
        for (int j = 0; j < 4; j++) {
            float2 v;
            asm("mov.b64 {%0,%1}, %2;" : "=f"(v.x), "=f"(v.y) : "l"(acc[i * 4 + j]));
            ob[(b0 + i) * F + fg + (j << 5)] = v;
        }
    }
}

// ---------------- K5: 2D irFFT + slice + bias ----------------
__global__ void __launch_bounds__(512) k_ifft(float* __restrict__ out,
                                              const float* __restrict__ bias) {
    extern __shared__ float2 sm[];
    float2* tw = sm;
    float2* bufA = sm + 128;
    float2* bufB = bufA + NBIN;
    int tid = threadIdx.x, nth = blockDim.x;
    int bf = blockIdx.x;
    int f  = bf & 127;

    make_twiddles(tw, tid);
    for (int bin = tid; bin < NBIN; bin += nth) {
        float2 v = g_of[(size_t)bin * BC + bf];
        int h = bin / NF, k = bin - h * NF;
        bufA[(k << 7) + swz(h)] = make_float2(v.x, -v.y);
    }
    __syncthreads();
    float2* R = fft128_r8(bufA, bufB, NF, tw, tid, nth);    // bufB
    float2* T = bufA;
    for (int idx = tid; idx < 64 * 128; idx += nth) {
        int r = idx >> 7, k = idx & 127;
        float2 val;
        if (k <= 64) {
            float2 a = R[(k << 7) + swz(2 * r)];
            float2 b = R[(k << 7) + swz(2 * r + 1)];
            val = make_float2(a.x + b.y, a.y - b.x);
        } else {
            int kk = 128 - k;
            float2 a = R[(kk << 7) + swz(2 * r)];
            float2 b = R[(kk << 7) + swz(2 * r + 1)];
            val = make_float2(a.x - b.y, -a.y - b.x);
        }
        T[(r << 7) + swz(k)] = val;
    }
    __syncthreads();
    float2* Y = fft128_r8(bufA, bufB, 64, tw, tid, nth);    // bufB
    const float inv = 1.0f / 16384.0f;
    float bv = bias[f];
    float* ob = out + (size_t)bf * OH * OW;
    for (int idx = tid; idx < OH * OW; idx += nth) {
        int oh = idx / OW, ow = idx - oh * OW;
        float2 y = Y[((oh >> 1) << 7) + swz(ow)];
        float v = (oh & 1) ? -y.y : y.x;
        ob[idx] = v * inv + bv;
    }
}

// ---------------- launch ----------------
extern "C" void kernel_launch(void* const* d_in, const int* in_sizes, int n_in,
                              void* d_out, int out_size) {
    const float* x    = (const float*)d_in[0];
    const float* filt = (const float*)d_in[1];
    const float* bias = (const float*)d_in[2];
    float* out = (float*)d_out;

    int smFFT  = (128 + 2 * NBIN) * (int)sizeof(float2);            // 134,144 B
    int smGEMM = 2 * BC * (int)sizeof(float2) + FC * 4;             // 98,304 B
    cudaFuncSetAttribute(k_fft_x, cudaFuncAttributeMaxDynamicSharedMemorySize, smFFT);
    cudaFuncSetAttribute(k_fft_k, cudaFuncAttributeMaxDynamicSharedMemorySize, smFFT);
    cudaFuncSetAttribute(k_ifft,  cudaFuncAttributeMaxDynamicSharedMemorySize, smFFT);
    cudaFuncSetAttribute(k_gemm,  cudaFuncAttributeMaxDynamicSharedMemorySize, smGEMM);

    k_fft_x<<<BC, 512, smFFT>>>(x);
    k_fft_k<<<FC, 512, smFFT>>>(filt);
    k_transpose<<<dim3(NBIN / 32, FC / 32), dim3(32, 8)>>>();
    k_gemm<<<NBIN, 128, smGEMM>>>();
    k_ifft<<<BC, 512, smFFT>>>(out, bias);
}

// round 6
// speedup vs baseline: 1.5101x; 1.2051x over previous
#include <cuda_runtime.h>
#include <cuda_fp16.h>
#include <cstdint>
#include <math.h>

#define BB 16
#define C  128
#define F  128
#define HH 128
#define WW 128
#define KHH 31
#define KWW 31
#define OH 98
#define OW 98
#define NF 65          // rfft bins along W
#define NBIN (HH*NF)   // 8320
#define BC (BB*C)      // 2048
#define FC (F*C)       // 16384

// -------- scratch (device globals; no allocation allowed) --------
__device__ float2  g_xf [(size_t)BC  * NBIN];   // [b*C+c][bin]
__device__ float2  g_xft[(size_t)NBIN * BC];    // [bin][b*C+c]
__device__ __half2 g_kfn[(size_t)FC  * NBIN];   // [c*F+f][bin]  (plain fft, fp16)
__device__ __half2 g_kft[(size_t)NBIN * FC];    // [bin][c*F+f]
__device__ float2  g_of [(size_t)NBIN * BC];    // [bin][b*F+f]

// ---------------- helpers ----------------
__device__ __forceinline__ int swz(int w) { return w ^ ((w >> 4) & 7); }
__device__ __forceinline__ float2 cadd(float2 a, float2 b){return make_float2(a.x+b.x, a.y+b.y);}
__device__ __forceinline__ float2 csub(float2 a, float2 b){return make_float2(a.x-b.x, a.y-b.y);}
__device__ __forceinline__ float2 cmul(float2 a, float2 b){return make_float2(a.x*b.x-a.y*b.y, a.x*b.y+a.y*b.x);}
__device__ __forceinline__ float2 cmulni(float2 a){return make_float2(a.y, -a.x);}  // a * (-i)

__device__ __forceinline__ void make_twiddles(float2* tw, int tid) {
    if (tid < 128) {
        float s, c;
        sincosf(-6.283185307179586f * (float)tid / 128.0f, &s, &c);
        tw[tid] = make_float2(c, s);
    }
}

__device__ __forceinline__ uint32_t smem_u32(const void* p) {
    uint32_t a;
    asm("{ .reg .u64 t; cvta.to.shared.u64 t, %1; cvt.u32.u64 %0, t; }" : "=r"(a) : "l"(p));
    return a;
}
__device__ __forceinline__ void cp16(uint32_t dst, const void* src) {
    asm volatile("cp.async.cg.shared.global [%0], [%1], 16;" :: "r"(dst), "l"(src));
}

// DFT8 natural order: c[k] = sum_j a[j] W8^{jk}
__device__ __forceinline__ void dft8(const float2* a, float2* c) {
    float2 t0 = cadd(a[0], a[4]), t1 = csub(a[0], a[4]);
    float2 t2 = cadd(a[2], a[6]), t3 = csub(a[2], a[6]);
    float2 m3 = cmulni(t3);
    float2 E0 = cadd(t0, t2), E2 = csub(t0, t2);
    float2 E1 = cadd(t1, m3), E3 = csub(t1, m3);
    t0 = cadd(a[1], a[5]); t1 = csub(a[1], a[5]);
    t2 = cadd(a[3], a[7]); t3 = csub(a[3], a[7]);
    m3 = cmulni(t3);
    float2 O0 = cadd(t0, t2), O2 = csub(t0, t2);
    float2 O1 = cadd(t1, m3), O3 = csub(t1, m3);
    const float s = 0.70710678118654752f;
    float2 w1o = make_float2(s * (O1.x + O1.y), s * (O1.y - O1.x));
    float2 w2o = cmulni(O2);
    float2 w3o = make_float2(s * (O3.y - O3.x), s * (-O3.x - O3.y));
    c[0] = cadd(E0, O0);  c[4] = csub(E0, O0);
    c[1] = cadd(E1, w1o); c[5] = csub(E1, w1o);
    c[2] = cadd(E2, w2o); c[6] = csub(E2, w2o);
    c[3] = cadd(E3, w3o); c[7] = csub(E3, w3o);
}

template<int M>
__device__ __forceinline__ void pass8(const float2* __restrict__ A, float2* __restrict__ B,
                                      int rows, const float2* __restrict__ tw, int tid, int nth) {
    int total = rows << 4;
    for (int idx = tid; idx < total; idx += nth) {
        int r = idx >> 4, t = idx & 15;
        int lo = t & (M - 1), hi = t - lo;
        int base = r << 7;
        float2 a[8], c[8];
        #pragma unroll
        for (int j = 0; j < 8; j++) a[j] = A[base + swz(t + 16 * j)];
        dft8(a, c);
        int p = 8 * hi + lo;
        B[base + swz(p)] = c[0];
        #pragma unroll
        for (int k = 1; k < 8; k++)
            B[base + swz(p + k * M)] = cmul(c[k], tw[(hi * k) & 127]);
    }
}

// sparse radix-8 first pass (M=1): only inputs 0..31 nonzero (j=0,1)
__device__ __forceinline__ void pass8_sp2(const float2* __restrict__ A, float2* __restrict__ B,
                                          int rows, const float2* __restrict__ tw, int tid, int nth) {
    int total = rows << 4;
    for (int idx = tid; idx < total; idx += nth) {
        int r = idx >> 4, t = idx & 15;
        int base = r << 7;
        float2 a0 = A[base + swz(t)];
        float2 a1 = A[base + swz(t + 16)];
        #pragma unroll
        for (int k = 0; k < 8; k++) {
            float2 ck = cadd(a0, cmul(a1, tw[(16 * k) & 127]));
            B[base + swz(8 * t + k)] = cmul(ck, tw[(t * k) & 127]);
        }
    }
}

__device__ __forceinline__ void pass2f(const float2* __restrict__ A, float2* __restrict__ B,
                                       int rows, int tid, int nth) {
    int total = rows << 6;
    for (int idx = tid; idx < total; idx += nth) {
        int r = idx >> 6, t = idx & 63;
        int base = r << 7;
        float2 a0 = A[base + swz(t)];
        float2 a1 = A[base + swz(t + 64)];
        B[base + swz(t)]      = cadd(a0, a1);
        B[base + swz(t + 64)] = csub(a0, a1);
    }
}

__device__ __forceinline__ float2* fft128_r8(float2* A, float2* B, int rows,
                                             const float2* tw, int tid, int nth) {
    pass8<1>(A, B, rows, tw, tid, nth); __syncthreads();
    pass8<8>(B, A, rows, tw, tid, nth); __syncthreads();
    pass2f(A, B, rows, tid, nth);       __syncthreads();
    return B;
}

// ---------------- K1: 2D rFFT of x -> g_xf[bc][bin] ----------------
__global__ void __launch_bounds__(512) k_fft_x(const float* __restrict__ x) {
    extern __shared__ float2 sm[];
    float2* tw = sm;
    float2* bufA = sm + 128;
    float2* bufB = bufA + NBIN;
    int tid = threadIdx.x, nth = blockDim.x;
    int bc = blockIdx.x;

    make_twiddles(tw, tid);
    const float* img = x + (size_t)bc * HH * WW;
    for (int idx = tid; idx < 64 * 128; idx += nth) {
        int r = idx >> 7, n = idx & 127;
        bufA[(r << 7) + swz(n)] = make_float2(img[(2 * r) * WW + n],
                                              img[(2 * r + 1) * WW + n]);
    }
    __syncthreads();
    float2* P = fft128_r8(bufA, bufB, 64, tw, tid, nth);
    float2* S = bufA;
    for (int idx = tid; idx < 64 * NF; idx += nth) {
        int r = idx / NF, k = idx - r * NF;
        float2 Zk = P[(r << 7) + swz(k)];
        float2 Zn = P[(r << 7) + swz((128 - k) & 127)];
        float2 Ar = make_float2(0.5f * (Zk.x + Zn.x), 0.5f * (Zk.y - Zn.y));
        float2 Br = make_float2(0.5f * (Zk.y + Zn.y), 0.5f * (Zn.x - Zk.x));
        S[(k << 7) + swz(2 * r)]     = Ar;
        S[(k << 7) + swz(2 * r + 1)] = Br;
    }
    __syncthreads();
    float2* Ff = fft128_r8(bufA, bufB, NF, tw, tid, nth);
    float2* ob = g_xf + (size_t)bc * NBIN;
    for (int bin = tid; bin < NBIN; bin += nth) {
        int h = bin / NF, k = bin - h * NF;
        ob[bin] = Ff[(k << 7) + swz(h)];
    }
}

// ---------------- K2: 2D rFFT of filters (plain, fp16) -> g_kfn[c*F+f][bin] ----------------
__global__ void __launch_bounds__(512) k_fft_k(const float* __restrict__ filt) {
    extern __shared__ float2 sm[];
    float2* tw = sm;
    float2* bufA = sm + 128;
    float2* bufB = bufA + NBIN;
    int tid = threadIdx.x, nth = blockDim.x;
    int fc = blockIdx.x;   // f*C + c (natural input order)
    int f = fc >> 7, c = fc & 127;

    make_twiddles(tw, tid);
    for (int idx = tid; idx < 16 * 128; idx += nth)
        bufA[idx] = make_float2(0.f, 0.f);
    __syncthreads();
    const float* kimg = filt + (size_t)fc * KHH * KWW;
    for (int idx = tid; idx < KHH * KWW; idx += nth) {
        int i = idx / KWW, j = idx - i * KWW;
        float v = kimg[idx];
        int r = i >> 1;
        if (i & 1) bufA[(r << 7) + swz(j)].y = v;
        else       bufA[(r << 7) + swz(j)].x = v;
    }
    __syncthreads();
    float2* P = fft128_r8(bufA, bufB, 16, tw, tid, nth);
    float2* S = bufA;
    for (int idx = tid; idx < 16 * NF; idx += nth) {
        int r = idx / NF, k = idx - r * NF;
        float2 Zk = P[(r << 7) + swz(k)];
        float2 Zn = P[(r << 7) + swz((128 - k) & 127)];
        float2 Ar = make_float2(0.5f * (Zk.x + Zn.x), 0.5f * (Zk.y - Zn.y));
        float2 Br = make_float2(0.5f * (Zk.y + Zn.y), 0.5f * (Zn.x - Zk.x));
        S[(k << 7) + swz(2 * r)]     = Ar;
        S[(k << 7) + swz(2 * r + 1)] = Br;
    }
    __syncthreads();
    pass8_sp2(bufA, bufB, NF, tw, tid, nth); __syncthreads();
    pass8<8>(bufB, bufA, NF, tw, tid, nth);  __syncthreads();
    pass2f(bufA, bufB, NF, tid, nth);        __syncthreads();
    float2* Ff = bufB;
    __half2* ob = g_kfn + (size_t)(c * F + f) * NBIN;   // row = c*F+f for [bin][c][f] layout
    for (int bin = tid; bin < NBIN; bin += nth) {
        int h = bin / NF, k = bin - h * NF;
        float2 v = Ff[(k << 7) + swz(h)];
        ob[bin] = __floats2half2_rn(v.x, v.y);   // plain fft (p, q)
    }
}

// ---------------- K3: transpose kf [cf][bin] -> [bin][cf] (4B elems) ----------------
__global__ void __launch_bounds__(256) k_transpose() {
    __shared__ unsigned int t[32][33];
    const unsigned int* src = (const unsigned int*)g_kfn;
    unsigned int* dst = (unsigned int*)g_kft;
    int x0 = blockIdx.x * 32;   // bin
    int y0 = blockIdx.y * 32;   // cf
    for (int i = threadIdx.y; i < 32; i += 8)
        t[i][threadIdx.x] = src[(size_t)(y0 + i) * NBIN + x0 + threadIdx.x];
    __syncthreads();
    for (int i = threadIdx.y; i < 32; i += 8)
        dst[(size_t)(x0 + i) * FC + y0 + threadIdx.x] = t[threadIdx.x][i];
}

// ---------------- K3x: transpose xf [bc][bin] -> [bin][bc] (8B elems) ----------------
__global__ void __launch_bounds__(256) k_transpose_x() {
    __shared__ float2 t[32][33];
    int x0 = blockIdx.x * 32;   // bin
    int y0 = blockIdx.y * 32;   // bc
    for (int i = threadIdx.y; i < 32; i += 8)
        t[i][threadIdx.x] = g_xf[(size_t)(y0 + i) * NBIN + x0 + threadIdx.x];
    __syncthreads();
    for (int i = threadIdx.y; i < 32; i += 8)
        g_xft[(size_t)(x0 + i) * BC + y0 + threadIdx.x] = t[threadIdx.x][i];
}

// ---------------- K4: per-bin complex GEMM via f32x2, cp.async-staged kf ----------------
// thread tile 4f x 4b.  f = 4*lane + j,  b = 4*wid + i.
// kf layout [bin][c][f] fp16 (p,q);  D = X * conj(K):
//   acc += (Xr,Xi) * (p,p)      [gives (Xr*p, Xi*p)]
//   acc += (Xi,-Xr) * (q,q)     [gives (Xi*q, -Xr*q)]
//   -> re = Xr*p + Xi*q, im = Xi*p - Xr*q  ✓
#define CH 16                         // c's per stage
#define K4_XS_BYTES (BC * 16)         // 32KB  float4 (Xr, Xi, Xi, -Xr)
#define K4_KS_BYTES (2 * CH * 512)    // 16KB  double-buffered kf stages
#define SMEM_K4 (K4_XS_BYTES + K4_KS_BYTES)

__global__ void __launch_bounds__(128, 4) k_gemm_fix() {
    extern __shared__ char s4[];
    float4* xs = (float4*)s4;                 // (Xr, Xi, Xi, -Xr)
    uint4*  ks = (uint4*)(s4 + K4_XS_BYTES);
    uint32_t ksb = smem_u32(ks);
    int tid = threadIdx.x, lane = tid & 31, wid = tid >> 5;
    int bin = blockIdx.x;

    const float2* gX = g_xft + (size_t)bin * BC;
    #pragma unroll
    for (int k = 0; k < 16; k++) {
        int i = k * 128 + tid;
        float2 v = gX[i];
        xs[i] = make_float4(v.x, v.y, v.y, -v.x);
    }
    const uint4* gK = (const uint4*)(g_kft + (size_t)bin * FC);   // 32 uint4 per c
    #pragma unroll
    for (int s = 0; s < 2; s++) {
        #pragma unroll
        for (int k = 0; k < 4; k++) {
            int m = k * 128 + tid;
            cp16(ksb + (s * 512 + m) * 16, gK + s * 512 + m);
        }
        asm volatile("cp.async.commit_group;");
    }
    __syncthreads();

    int b0 = wid * 4;
    unsigned long long acc[16];
    #pragma unroll
    for (int i = 0; i < 16; i++) acc[i] = 0ULL;

    #pragma unroll 1
    for (int blk = 0; blk < 8; blk++) {
        if (blk < 7) asm volatile("cp.async.wait_group 1;");
        else         asm volatile("cp.async.wait_group 0;");
        __syncthreads();
        const uint4* kb = ks + (blk & 1) * 512;
        #pragma unroll
        for (int cc = 0; cc < CH; cc++) {
            int c = blk * CH + cc;
            uint4 kq = kb[cc * 32 + lane];          // 4 half2: kf for f=4*lane..4*lane+3
            unsigned long long x1[4], x2[4];
            #pragma unroll
            for (int i = 0; i < 4; i++) {
                float4 xv = xs[(b0 + i) * C + c];   // broadcast LDS
                asm("mov.b64 %0, {%1,%2};" : "=l"(x1[i]) : "f"(xv.x), "f"(xv.y));  // (Xr, Xi)
                asm("mov.b64 %0, {%1,%2};" : "=l"(x2[i]) : "f"(xv.z), "f"(xv.w));  // (Xi, -Xr)
            }
            uint32_t kw[4] = {kq.x, kq.y, kq.z, kq.w};
            #pragma unroll
            for (int j = 0; j < 4; j++) {
                float2 kv = __half22float2(*reinterpret_cast<__half2*>(&kw[j]));   // (p, q)
                unsigned long long Kp, Kq;
                asm("mov.b64 %0, {%1,%2};" : "=l"(Kp) : "f"(kv.x), "f"(kv.x));     // (p, p)
                asm("mov.b64 %0, {%1,%2};" : "=l"(Kq) : "f"(kv.y), "f"(kv.y));     // (q, q)
                #pragma unroll
                for (int i = 0; i < 4; i++) {
                    asm("fma.rn.f32x2 %0, %1, %2, %0;" : "+l"(acc[i * 4 + j]) : "l"(x1[i]), "l"(Kp));
                    asm("fma.rn.f32x2 %0, %1, %2, %0;" : "+l"(acc[i * 4 + j]) : "l"(x2[i]), "l"(Kq));
                }
            }
        }
        __syncthreads();
        if (blk < 6) {
            #pragma unroll
            for (int k = 0; k < 4; k++) {
                int m = k * 128 + tid;
                cp16(ksb + ((blk & 1) * 512 + m) * 16, gK + (blk + 2) * 512 + m);
            }
        }
        asm volatile("cp.async.commit_group;");
    }

    // store: thread owns f = 4*lane..4*lane+3 -> 32B contiguous per b
    float2* ob = g_of + (size_t)bin * BC;
    #pragma unroll
    for (int i = 0; i < 4; i++) {
        float2 v[4];
        #pragma unroll
        for (int j = 0; j < 4; j++)
            asm("mov.b64 {%0,%1}, %2;" : "=f"(v[j].x), "=f"(v[j].y) : "l"(acc[i * 4 + j]));
        float4* dst = (float4*)&ob[(b0 + i) * F + 4 * lane];
        dst[0] = make_float4(v[0].x, v[0].y, v[1].x, v[1].y);
        dst[1] = make_float4(v[2].x, v[2].y, v[3].x, v[3].y);
    }
}

// ---------------- K5: 2D irFFT + slice + bias ----------------
__global__ void __launch_bounds__(512) k_ifft(float* __restrict__ out,
                                              const float* __restrict__ bias) {
    extern __shared__ float2 sm[];
    float2* tw = sm;
    float2* bufA = sm + 128;
    float2* bufB = bufA + NBIN;
    int tid = threadIdx.x, nth = blockDim.x;
    int bf = blockIdx.x;
    int f  = bf & 127;

    make_twiddles(tw, tid);
    for (int bin = tid; bin < NBIN; bin += nth) {
        float2 v = g_of[(size_t)bin * BC + bf];
        int h = bin / NF, k = bin - h * NF;
        bufA[(k << 7) + swz(h)] = make_float2(v.x, -v.y);
    }
    __syncthreads();
    float2* R = fft128_r8(bufA, bufB, NF, tw, tid, nth);
    float2* T = bufA;
    for (int idx = tid; idx < 64 * 128; idx += nth) {
        int r = idx >> 7, k = idx & 127;
        float2 val;
        if (k <= 64) {
            float2 a = R[(k << 7) + swz(2 * r)];
            float2 b = R[(k << 7) + swz(2 * r + 1)];
            val = make_float2(a.x + b.y, a.y - b.x);
        } else {
            int kk = 128 - k;
            float2 a = R[(kk << 7) + swz(2 * r)];
            float2 b = R[(kk << 7) + swz(2 * r + 1)];
            val = make_float2(a.x - b.y, -a.y - b.x);
        }
        T[(r << 7) + swz(k)] = val;
    }
    __syncthreads();
    float2* Y = fft128_r8(bufA, bufB, 64, tw, tid, nth);
    const float inv = 1.0f / 16384.0f;
    float bv = bias[f];
    float* ob = out + (size_t)bf * OH * OW;
    for (int idx = tid; idx < OH * OW; idx += nth) {
        int oh = idx / OW, ow = idx - oh * OW;
        float2 y = Y[((oh >> 1) << 7) + swz(ow)];
        float v = (oh & 1) ? -y.y : y.x;
        ob[idx] = v * inv + bv;
    }
}

// ---------------- launch ----------------
extern "C" void kernel_launch(void* const* d_in, const int* in_sizes, int n_in,
                              void* d_out, int out_size) {
    const float* x    = (const float*)d_in[0];
    const float* filt = (const float*)d_in[1];
    const float* bias = (const float*)d_in[2];
    float* out = (float*)d_out;

    int smFFT = (128 + 2 * NBIN) * (int)sizeof(float2);   // 134,144 B
    cudaFuncSetAttribute(k_fft_x,    cudaFuncAttributeMaxDynamicSharedMemorySize, smFFT);
    cudaFuncSetAttribute(k_fft_k,    cudaFuncAttributeMaxDynamicSharedMemorySize, smFFT);
    cudaFuncSetAttribute(k_ifft,     cudaFuncAttributeMaxDynamicSharedMemorySize, smFFT);
    cudaFuncSetAttribute(k_gemm_fix, cudaFuncAttributeMaxDynamicSharedMemorySize, SMEM_K4);

    k_fft_x<<<BC, 512, smFFT>>>(x);
    k_fft_k<<<FC, 512, smFFT>>>(filt);
    k_transpose<<<dim3(NBIN / 32, FC / 32), dim3(32, 8)>>>();
    k_transpose_x<<<dim3(NBIN / 32, BC / 32), dim3(32, 8)>>>();
    k_gemm_fix<<<NBIN, 128, SMEM_K4>>>();
    k_ifft<<<BC, 512, smFFT>>>(out, bias);
}

// round 7
// speedup vs baseline: 2.0357x; 1.3481x over previous
#include <cuda_runtime.h>
#include <cuda_fp16.h>
#include <cstdint>
#include <math.h>

#define BB 16
#define C  128
#define F  128
#define HH 128
#define WW 128
#define KHH 31
#define KWW 31
#define OH 98
#define OW 98
#define NF 65          // rfft bins along W
#define NBIN (HH*NF)   // 8320 ; bin = k*128 + h  (k-major)
#define BC (BB*C)      // 2048
#define FC (F*C)       // 16384

// -------- scratch (device globals; no allocation allowed) --------
__device__ float2  g_xf [(size_t)BC  * NBIN];   // [b*C+c][bin]; later reused as of^T [b*F+f][bin]
__device__ float2  g_xft[(size_t)NBIN * BC];    // [bin][b*C+c]
__device__ __half2 g_kfn[(size_t)FC  * NBIN];   // [c*F+f][bin]  (plain fft, fp16)
__device__ __half2 g_kft[(size_t)NBIN * FC];    // [bin][c*F+f]
__device__ float2  g_of [(size_t)NBIN * BC];    // [bin][b*F+f]

// ---------------- helpers ----------------
__device__ __forceinline__ int swz(int w) { return w ^ ((w >> 4) & 7); }
__device__ __forceinline__ float2 cadd(float2 a, float2 b){return make_float2(a.x+b.x, a.y+b.y);}
__device__ __forceinline__ float2 csub(float2 a, float2 b){return make_float2(a.x-b.x, a.y-b.y);}
__device__ __forceinline__ float2 cmul(float2 a, float2 b){return make_float2(a.x*b.x-a.y*b.y, a.x*b.y+a.y*b.x);}
__device__ __forceinline__ float2 cmulni(float2 a){return make_float2(a.y, -a.x);}  // a * (-i)

__device__ __forceinline__ void make_twiddles(float2* tw, int tid) {
    if (tid < 128) {
        float s, c;
        sincosf(-6.283185307179586f * (float)tid / 128.0f, &s, &c);
        tw[tid] = make_float2(c, s);
    }
}

__device__ __forceinline__ uint32_t smem_u32(const void* p) {
    uint32_t a;
    asm("{ .reg .u64 t; cvta.to.shared.u64 t, %1; cvt.u32.u64 %0, t; }" : "=r"(a) : "l"(p));
    return a;
}
__device__ __forceinline__ void cp16(uint32_t dst, const void* src) {
    asm volatile("cp.async.cg.shared.global [%0], [%1], 16;" :: "r"(dst), "l"(src));
}

// DFT8 natural order: c[k] = sum_j a[j] W8^{jk}
__device__ __forceinline__ void dft8(const float2* a, float2* c) {
    float2 t0 = cadd(a[0], a[4]), t1 = csub(a[0], a[4]);
    float2 t2 = cadd(a[2], a[6]), t3 = csub(a[2], a[6]);
    float2 m3 = cmulni(t3);
    float2 E0 = cadd(t0, t2), E2 = csub(t0, t2);
    float2 E1 = cadd(t1, m3), E3 = csub(t1, m3);
    t0 = cadd(a[1], a[5]); t1 = csub(a[1], a[5]);
    t2 = cadd(a[3], a[7]); t3 = csub(a[3], a[7]);
    m3 = cmulni(t3);
    float2 O0 = cadd(t0, t2), O2 = csub(t0, t2);
    float2 O1 = cadd(t1, m3), O3 = csub(t1, m3);
    const float s = 0.70710678118654752f;
    float2 w1o = make_float2(s * (O1.x + O1.y), s * (O1.y - O1.x));
    float2 w2o = cmulni(O2);
    float2 w3o = make_float2(s * (O3.y - O3.x), s * (-O3.x - O3.y));
    c[0] = cadd(E0, O0);  c[4] = csub(E0, O0);
    c[1] = cadd(E1, w1o); c[5] = csub(E1, w1o);
    c[2] = cadd(E2, w2o); c[6] = csub(E2, w2o);
    c[3] = cadd(E3, w3o); c[7] = csub(E3, w3o);
}

// ---------- fp32 Stockham passes ----------
template<int M>
__device__ __forceinline__ void pass8(const float2* __restrict__ A, float2* __restrict__ B,
                                      int rows, const float2* __restrict__ tw, int tid, int nth) {
    int total = rows << 4;
    for (int idx = tid; idx < total; idx += nth) {
        int r = idx >> 4, t = idx & 15;
        int lo = t & (M - 1), hi = t - lo;
        int base = r << 7;
        float2 a[8], c[8];
        #pragma unroll
        for (int j = 0; j < 8; j++) a[j] = A[base + swz(t + 16 * j)];
        dft8(a, c);
        int p = 8 * hi + lo;
        B[base + swz(p)] = c[0];
        #pragma unroll
        for (int k = 1; k < 8; k++)
            B[base + swz(p + k * M)] = cmul(c[k], tw[(hi * k) & 127]);
    }
}

__device__ __forceinline__ void pass2f(const float2* __restrict__ A, float2* __restrict__ B,
                                       int rows, int tid, int nth) {
    int total = rows << 6;
    for (int idx = tid; idx < total; idx += nth) {
        int r = idx >> 6, t = idx & 63;
        int base = r << 7;
        float2 a0 = A[base + swz(t)];
        float2 a1 = A[base + swz(t + 64)];
        B[base + swz(t)]      = cadd(a0, a1);
        B[base + swz(t + 64)] = csub(a0, a1);
    }
}

__device__ __forceinline__ float2* fft128_r8(float2* A, float2* B, int rows,
                                             const float2* tw, int tid, int nth) {
    pass8<1>(A, B, rows, tw, tid, nth); __syncthreads();
    pass8<8>(B, A, rows, tw, tid, nth); __syncthreads();
    pass2f(A, B, rows, tid, nth);       __syncthreads();
    return B;
}

// ---------- fp16-storage Stockham passes (fp32 compute) ----------
__device__ __forceinline__ float2 h2f(__half2 v){ return __half22float2(v); }
__device__ __forceinline__ __half2 f2h(float2 v){ return __floats2half2_rn(v.x, v.y); }

// sparse radix-8 first pass (M=1): only inputs 0..31 nonzero
__device__ __forceinline__ void pass8h_sp2(const __half2* __restrict__ A, __half2* __restrict__ B,
                                           int rows, const float2* __restrict__ tw, int tid, int nth) {
    int total = rows << 4;
    for (int idx = tid; idx < total; idx += nth) {
        int r = idx >> 4, t = idx & 15;
        int base = r << 7;
        float2 a0 = h2f(A[base + swz(t)]);
        float2 a1 = h2f(A[base + swz(t + 16)]);
        #pragma unroll
        for (int k = 0; k < 8; k++) {
            float2 ck = cadd(a0, cmul(a1, tw[(16 * k) & 127]));
            B[base + swz(8 * t + k)] = f2h(cmul(ck, tw[(t * k) & 127]));
        }
    }
}

template<int M>
__device__ __forceinline__ void pass8h(const __half2* __restrict__ A, __half2* __restrict__ B,
                                       int rows, const float2* __restrict__ tw, int tid, int nth) {
    int total = rows << 4;
    for (int idx = tid; idx < total; idx += nth) {
        int r = idx >> 4, t = idx & 15;
        int lo = t & (M - 1), hi = t - lo;
        int base = r << 7;
        float2 a[8], c[8];
        #pragma unroll
        for (int j = 0; j < 8; j++) a[j] = h2f(A[base + swz(t + 16 * j)]);
        dft8(a, c);
        int p = 8 * hi + lo;
        B[base + swz(p)] = f2h(c[0]);
        #pragma unroll
        for (int k = 1; k < 8; k++)
            B[base + swz(p + k * M)] = f2h(cmul(c[k], tw[(hi * k) & 127]));
    }
}

__device__ __forceinline__ void pass2fh(const __half2* __restrict__ A, __half2* __restrict__ B,
                                        int rows, int tid, int nth) {
    int total = rows << 6;
    for (int idx = tid; idx < total; idx += nth) {
        int r = idx >> 6, t = idx & 63;
        int base = r << 7;
        float2 a0 = h2f(A[base + swz(t)]);
        float2 a1 = h2f(A[base + swz(t + 64)]);
        B[base + swz(t)]      = f2h(cadd(a0, a1));
        B[base + swz(t + 64)] = f2h(csub(a0, a1));
    }
}

// ---------------- K1: 2D rFFT of x -> g_xf[bc][bin] ----------------
__global__ void __launch_bounds__(512) k_fft_x(const float* __restrict__ x) {
    extern __shared__ float2 sm[];
    float2* tw = sm;
    float2* bufA = sm + 128;
    float2* bufB = bufA + NBIN;
    int tid = threadIdx.x, nth = blockDim.x;
    int bc = blockIdx.x;

    make_twiddles(tw, tid);
    const float* img = x + (size_t)bc * HH * WW;
    for (int idx = tid; idx < 64 * 128; idx += nth) {
        int r = idx >> 7, n = idx & 127;
        bufA[(r << 7) + swz(n)] = make_float2(img[(2 * r) * WW + n],
                                              img[(2 * r + 1) * WW + n]);
    }
    __syncthreads();
    float2* P = fft128_r8(bufA, bufB, 64, tw, tid, nth);
    float2* S = bufA;
    for (int idx = tid; idx < 64 * NF; idx += nth) {
        int r = idx / NF, k = idx - r * NF;
        float2 Zk = P[(r << 7) + swz(k)];
        float2 Zn = P[(r << 7) + swz((128 - k) & 127)];
        float2 Ar = make_float2(0.5f * (Zk.x + Zn.x), 0.5f * (Zk.y - Zn.y));
        float2 Br = make_float2(0.5f * (Zk.y + Zn.y), 0.5f * (Zn.x - Zk.x));
        S[(k << 7) + swz(2 * r)]     = Ar;
        S[(k << 7) + swz(2 * r + 1)] = Br;
    }
    __syncthreads();
    float2* Ff = fft128_r8(bufA, bufB, NF, tw, tid, nth);
    float2* ob = g_xf + (size_t)bc * NBIN;
    for (int bin = tid; bin < NBIN; bin += nth) {
        int h = bin & 127;
        ob[bin] = Ff[(bin - h) + swz(h)];    // bin = k*128+h ; (k<<7) = bin-h
    }
}

// ---------------- K2: 2D rFFT of filters (plain, fp16) -> g_kfn[c*F+f][bin] ----------------
// smem: tw(1KB) | CA half2[NBIN] | CB half2[NBIN]; row bufs RA/RB (fp32) aliased inside CB.
#define SMEM_K2 (1024 + 2 * NBIN * 4)    // 67,584 B
__global__ void __launch_bounds__(512, 2) k_fft_k(const float* __restrict__ filt) {
    extern __shared__ char smk[];
    float2*  tw = (float2*)smk;
    __half2* CA = (__half2*)(smk + 1024);
    __half2* CB = (__half2*)(smk + 1024 + NBIN * 4);
    float2*  RA = (float2*)CB;                              // 16 KB
    float2*  RB = (float2*)(smk + 1024 + NBIN * 4 + 16384); // 16 KB (inside CB region)
    int tid = threadIdx.x, nth = blockDim.x;
    int fc = blockIdx.x;   // f*C + c (natural input order)
    int f = fc >> 7, c = fc & 127;

    make_twiddles(tw, tid);
    for (int idx = tid; idx < 16 * 128; idx += nth)
        RA[idx] = make_float2(0.f, 0.f);
    __syncthreads();
    const float* kimg = filt + (size_t)fc * KHH * KWW;
    for (int idx = tid; idx < KHH * KWW; idx += nth) {
        int i = idx / KWW, j = idx - i * KWW;
        float v = kimg[idx];
        int r = i >> 1;
        if (i & 1) RA[(r << 7) + swz(j)].y = v;
        else       RA[(r << 7) + swz(j)].x = v;
    }
    __syncthreads();
    float2* P = fft128_r8(RA, RB, 16, tw, tid, nth);   // result in RB
    // unpack rfft rows -> CA[k][h] (h < 32 only; those are all the col-FFT inputs)
    for (int idx = tid; idx < 16 * NF; idx += nth) {
        int r = idx / NF, k = idx - r * NF;
        float2 Zk = P[(r << 7) + swz(k)];
        float2 Zn = P[(r << 7) + swz((128 - k) & 127)];
        float2 Ar = make_float2(0.5f * (Zk.x + Zn.x), 0.5f * (Zk.y - Zn.y));
        float2 Br = make_float2(0.5f * (Zk.y + Zn.y), 0.5f * (Zn.x - Zk.x));
        CA[(k << 7) + swz(2 * r)]     = f2h(Ar);
        CA[(k << 7) + swz(2 * r + 1)] = f2h(Br);
    }
    __syncthreads();
    // column FFT (65 rows), sparse first pass; clobbers RA/RB (CB region) — OK
    pass8h_sp2(CA, CB, NF, tw, tid, nth); __syncthreads();
    pass8h<8>(CB, CA, NF, tw, tid, nth);  __syncthreads();
    pass2fh(CA, CB, NF, tid, nth);        __syncthreads();
    __half2* ob = g_kfn + (size_t)(c * F + f) * NBIN;   // row = c*F+f for [bin][c][f] layout
    for (int bin = tid; bin < NBIN; bin += nth) {
        int h = bin & 127;
        ob[bin] = CB[(bin - h) + swz(h)];
    }
}

// ---------------- K3: transpose kf [cf][bin] -> [bin][cf] (4B elems) ----------------
__global__ void __launch_bounds__(256) k_transpose() {
    __shared__ unsigned int t[32][33];
    const unsigned int* src = (const unsigned int*)g_kfn;
    unsigned int* dst = (unsigned int*)g_kft;
    int x0 = blockIdx.x * 32;   // bin
    int y0 = blockIdx.y * 32;   // cf
    for (int i = threadIdx.y; i < 32; i += 8)
        t[i][threadIdx.x] = src[(size_t)(y0 + i) * NBIN + x0 + threadIdx.x];
    __syncthreads();
    for (int i = threadIdx.y; i < 32; i += 8)
        dst[(size_t)(x0 + i) * FC + y0 + threadIdx.x] = t[threadIdx.x][i];
}

// ---------------- K3x: transpose xf [bc][bin] -> [bin][bc] (8B elems) ----------------
__global__ void __launch_bounds__(256) k_transpose_x() {
    __shared__ float2 t[32][33];
    int x0 = blockIdx.x * 32;   // bin
    int y0 = blockIdx.y * 32;   // bc
    for (int i = threadIdx.y; i < 32; i += 8)
        t[i][threadIdx.x] = g_xf[(size_t)(y0 + i) * NBIN + x0 + threadIdx.x];
    __syncthreads();
    for (int i = threadIdx.y; i < 32; i += 8)
        g_xft[(size_t)(x0 + i) * BC + y0 + threadIdx.x] = t[threadIdx.x][i];
}

// ---------------- K3o: transpose of [bin][bf] -> g_xf (reused) [bf][bin] ----------------
__global__ void __launch_bounds__(256) k_transpose_of() {
    __shared__ float2 t[32][33];
    int b0 = blockIdx.x * 32;   // bin
    int f0 = blockIdx.y * 32;   // bf
    for (int i = threadIdx.y; i < 32; i += 8)
        t[i][threadIdx.x] = g_of[(size_t)(b0 + i) * BC + f0 + threadIdx.x];
    __syncthreads();
    for (int i = threadIdx.y; i < 32; i += 8)
        g_xf[(size_t)(f0 + i) * NBIN + b0 + threadIdx.x] = t[threadIdx.x][i];
}

// ---------------- K4: per-bin complex GEMM via f32x2, cp.async-staged kf ----------------
// thread tile 4f x 4b.  f = 4*lane + j,  b = 4*wid + i.
// kf layout [bin][c][f] fp16 (p,q);  D = X * conj(K):
//   acc += (Xr,Xi) * (p,p)  +  (Xi,-Xr) * (q,q)   -> (Xr*p + Xi*q, Xi*p - Xr*q) ✓
#define CH 16                         // c's per stage
#define K4_XS_BYTES (BC * 16)         // 32KB  float4 (Xr, Xi, Xi, -Xr)
#define K4_KS_BYTES (2 * CH * 512)    // 16KB  double-buffered kf stages
#define SMEM_K4 (K4_XS_BYTES + K4_KS_BYTES)

__global__ void __launch_bounds__(128, 4) k_gemm_fix() {
    extern __shared__ char s4[];
    float4* xs = (float4*)s4;                 // (Xr, Xi, Xi, -Xr)
    uint4*  ks = (uint4*)(s4 + K4_XS_BYTES);
    uint32_t ksb = smem_u32(ks);
    int tid = threadIdx.x, lane = tid & 31, wid = tid >> 5;
    int bin = blockIdx.x;

    const float2* gX = g_xft + (size_t)bin * BC;
    #pragma unroll
    for (int k = 0; k < 16; k++) {
        int i = k * 128 + tid;
        float2 v = gX[i];
        xs[i] = make_float4(v.x, v.y, v.y, -v.x);
    }
    const uint4* gK = (const uint4*)(g_kft + (size_t)bin * FC);   // 32 uint4 per c
    #pragma unroll
    for (int s = 0; s < 2; s++) {
        #pragma unroll
        for (int k = 0; k < 4; k++) {
            int m = k * 128 + tid;
            cp16(ksb + (s * 512 + m) * 16, gK + s * 512 + m);
        }
        asm volatile("cp.async.commit_group;");
    }
    __syncthreads();

    int b0 = wid * 4;
    unsigned long long acc[16];
    #pragma unroll
    for (int i = 0; i < 16; i++) acc[i] = 0ULL;

    #pragma unroll 1
    for (int blk = 0; blk < 8; blk++) {
        if (blk < 7) asm volatile("cp.async.wait_group 1;");
        else         asm volatile("cp.async.wait_group 0;");
        __syncthreads();
        const uint4* kb = ks + (blk & 1) * 512;
        #pragma unroll
        for (int cc = 0; cc < CH; cc++) {
            int c = blk * CH + cc;
            uint4 kq = kb[cc * 32 + lane];          // 4 half2: kf for f=4*lane..4*lane+3
            unsigned long long x1[4], x2[4];
            #pragma unroll
            for (int i = 0; i < 4; i++) {
                float4 xv = xs[(b0 + i) * C + c];   // broadcast LDS
                asm("mov.b64 %0, {%1,%2};" : "=l"(x1[i]) : "f"(xv.x), "f"(xv.y));  // (Xr, Xi)
                asm("mov.b64 %0, {%1,%2};" : "=l"(x2[i]) : "f"(xv.z), "f"(xv.w));  // (Xi, -Xr)
            }
            uint32_t kw[4] = {kq.x, kq.y, kq.z, kq.w};
            #pragma unroll
            for (int j = 0; j < 4; j++) {
                float2 kv = __half22float2(*reinterpret_cast<__half2*>(&kw[j]));   // (p, q)
                unsigned long long Kp, Kq;
                asm("mov.b64 %0, {%1,%2};" : "=l"(Kp) : "f"(kv.x), "f"(kv.x));     // (p, p)
                asm("mov.b64 %0, {%1,%2};" : "=l"(Kq) : "f"(kv.y), "f"(kv.y));     // (q, q)
                #pragma unroll
                for (int i = 0; i < 4; i++) {
                    asm("fma.rn.f32x2 %0, %1, %2, %0;" : "+l"(acc[i * 4 + j]) : "l"(x1[i]), "l"(Kp));
                    asm("fma.rn.f32x2 %0, %1, %2, %0;" : "+l"(acc[i * 4 + j]) : "l"(x2[i]), "l"(Kq));
                }
            }
        }
        __syncthreads();
        if (blk < 6) {
            #pragma unroll
            for (int k = 0; k < 4; k++) {
                int m = k * 128 + tid;
                cp16(ksb + ((blk & 1) * 512 + m) * 16, gK + (blk + 2) * 512 + m);
            }
        }
        asm volatile("cp.async.commit_group;");
    }

    float2* ob = g_of + (size_t)bin * BC;
    #pragma unroll
    for (int i = 0; i < 4; i++) {
        float2 v[4];
        #pragma unroll
        for (int j = 0; j < 4; j++)
            asm("mov.b64 {%0,%1}, %2;" : "=f"(v[j].x), "=f"(v[j].y) : "l"(acc[i * 4 + j]));
        float4* dst = (float4*)&ob[(b0 + i) * F + 4 * lane];
        dst[0] = make_float4(v[0].x, v[0].y, v[1].x, v[1].y);
        dst[1] = make_float4(v[2].x, v[2].y, v[3].x, v[3].y);
    }
}

// ---------------- K5: 2D irFFT + slice + bias (reads of^T from g_xf) ----------------
__global__ void __launch_bounds__(512) k_ifft(float* __restrict__ out,
                                              const float* __restrict__ bias) {
    extern __shared__ float2 sm[];
    float2* tw = sm;
    float2* bufA = sm + 128;
    float2* bufB = bufA + NBIN;
    int tid = threadIdx.x, nth = blockDim.x;
    int bf = blockIdx.x;
    int f  = bf & 127;

    make_twiddles(tw, tid);
    const float2* src = g_xf + (size_t)bf * NBIN;    // of^T row, coalesced
    for (int bin = tid; bin < NBIN; bin += nth) {
        float2 v = src[bin];
        int h = bin & 127;
        bufA[(bin - h) + swz(h)] = make_float2(v.x, -v.y);
    }
    __syncthreads();
    float2* R = fft128_r8(bufA, bufB, NF, tw, tid, nth);
    float2* T = bufA;
    for (int idx = tid; idx < 64 * 128; idx += nth) {
        int r = idx >> 7, k = idx & 127;
        float2 val;
        if (k <= 64) {
            float2 a = R[(k << 7) + swz(2 * r)];
            float2 b = R[(k << 7) + swz(2 * r + 1)];
            val = make_float2(a.x + b.y, a.y - b.x);
        } else {
            int kk = 128 - k;
            float2 a = R[(kk << 7) + swz(2 * r)];
            float2 b = R[(kk << 7) + swz(2 * r + 1)];
            val = make_float2(a.x - b.y, -a.y - b.x);
        }
        T[(r << 7) + swz(k)] = val;
    }
    __syncthreads();
    float2* Y = fft128_r8(bufA, bufB, 64, tw, tid, nth);
    const float inv = 1.0f / 16384.0f;
    float bv = bias[f];
    float* ob = out + (size_t)bf * OH * OW;
    for (int idx = tid; idx < OH * OW; idx += nth) {
        int oh = idx / OW, ow = idx - oh * OW;
        float2 y = Y[((oh >> 1) << 7) + swz(ow)];
        float v = (oh & 1) ? -y.y : y.x;
        ob[idx] = v * inv + bv;
    }
}

// ---------------- launch ----------------
extern "C" void kernel_launch(void* const* d_in, const int* in_sizes, int n_in,
                              void* d_out, int out_size) {
    const float* x    = (const float*)d_in[0];
    const float* filt = (const float*)d_in[1];
    const float* bias = (const float*)d_in[2];
    float* out = (float*)d_out;

    int smFFT = (128 + 2 * NBIN) * (int)sizeof(float2);   // 134,144 B
    cudaFuncSetAttribute(k_fft_x,    cudaFuncAttributeMaxDynamicSharedMemorySize, smFFT);
    cudaFuncSetAttribute(k_fft_k,    cudaFuncAttributeMaxDynamicSharedMemorySize, SMEM_K2);
    cudaFuncSetAttribute(k_ifft,     cudaFuncAttributeMaxDynamicSharedMemorySize, smFFT);
    cudaFuncSetAttribute(k_gemm_fix, cudaFuncAttributeMaxDynamicSharedMemorySize, SMEM_K4);

    k_fft_x<<<BC, 512, smFFT>>>(x);
    k_fft_k<<<FC, 512, SMEM_K2>>>(filt);
    k_transpose<<<dim3(NBIN / 32, FC / 32), dim3(32, 8)>>>();
    k_transpose_x<<<dim3(NBIN / 32, BC / 32), dim3(32, 8)>>>();
    k_gemm_fix<<<NBIN, 128, SMEM_K4>>>();
    k_transpose_of<<<dim3(NBIN / 32, BC / 32), dim3(32, 8)>>>();
    k_ifft<<<BC, 512, smFFT>>>(out, bias);
}

// round 9
// speedup vs baseline: 2.2075x; 1.0844x over previous
#include <cuda_runtime.h>
#include <cuda_fp16.h>
#include <cstdint>
#include <math.h>

#define BB 16
#define C  128
#define F  128
#define HH 128
#define WW 128
#define KHH 31
#define KWW 31
#define OH 98
#define OW 98
#define NF 65          // rfft bins along W
#define NBIN (HH*NF)   // 8320 ; bin = k*128 + h  (k-major)
#define BC (BB*C)      // 2048
#define FC (F*C)       // 16384

// -------- scratch (device globals; no allocation allowed) --------
__device__ float2  g_xf [(size_t)BC  * NBIN];   // [b*C+c][bin]; later reused as of^T [b*F+f][bin]
__device__ float2  g_xft[(size_t)NBIN * BC];    // [bin][b*C+c]
__device__ __half2 g_kfn[(size_t)FC  * NBIN];   // [c*F+f][bin]  (plain fft, fp16)
__device__ __half2 g_kft[(size_t)NBIN * FC];    // [bin][c*F+f]
__device__ float2  g_of [(size_t)NBIN * BC];    // [bin][b*F+f]

// ---------------- helpers ----------------
__device__ __forceinline__ int swz(int w) { return w ^ ((w >> 4) & 7); }
// row-aware swizzle for k_fft_k buffers (kills cross-row bank alignment)
__device__ __forceinline__ int swzc(int r, int w) {
    int v = w ^ ((r & 3) << 3);
    return v ^ ((v >> 4) & 7);
}
__device__ __forceinline__ float2 cadd(float2 a, float2 b){return make_float2(a.x+b.x, a.y+b.y);}
__device__ __forceinline__ float2 csub(float2 a, float2 b){return make_float2(a.x-b.x, a.y-b.y);}
__device__ __forceinline__ float2 cmul(float2 a, float2 b){return make_float2(a.x*b.x-a.y*b.y, a.x*b.y+a.y*b.x);}
__device__ __forceinline__ float2 cmulni(float2 a){return make_float2(a.y, -a.x);}  // a * (-i)

__device__ __forceinline__ void make_twiddles(float2* tw, int tid) {
    if (tid < 128) {
        float s, c;
        sincosf(-6.283185307179586f * (float)tid / 128.0f, &s, &c);
        tw[tid] = make_float2(c, s);
    }
}

__device__ __forceinline__ uint32_t smem_u32(const void* p) {
    uint32_t a;
    asm("{ .reg .u64 t; cvta.to.shared.u64 t, %1; cvt.u32.u64 %0, t; }" : "=r"(a) : "l"(p));
    return a;
}
__device__ __forceinline__ void cp16(uint32_t dst, const void* src) {
    asm volatile("cp.async.cg.shared.global [%0], [%1], 16;" :: "r"(dst), "l"(src));
}

// DFT8 natural order: c[k] = sum_j a[j] W8^{jk}
__device__ __forceinline__ void dft8(const float2* a, float2* c) {
    float2 t0 = cadd(a[0], a[4]), t1 = csub(a[0], a[4]);
    float2 t2 = cadd(a[2], a[6]), t3 = csub(a[2], a[6]);
    float2 m3 = cmulni(t3);
    float2 E0 = cadd(t0, t2), E2 = csub(t0, t2);
    float2 E1 = cadd(t1, m3), E3 = csub(t1, m3);
    t0 = cadd(a[1], a[5]); t1 = csub(a[1], a[5]);
    t2 = cadd(a[3], a[7]); t3 = csub(a[3], a[7]);
    m3 = cmulni(t3);
    float2 O0 = cadd(t0, t2), O2 = csub(t0, t2);
    float2 O1 = cadd(t1, m3), O3 = csub(t1, m3);
    const float s = 0.70710678118654752f;
    float2 w1o = make_float2(s * (O1.x + O1.y), s * (O1.y - O1.x));
    float2 w2o = cmulni(O2);
    float2 w3o = make_float2(s * (O3.y - O3.x), s * (-O3.x - O3.y));
    c[0] = cadd(E0, O0);  c[4] = csub(E0, O0);
    c[1] = cadd(E1, w1o); c[5] = csub(E1, w1o);
    c[2] = cadd(E2, w2o); c[6] = csub(E2, w2o);
    c[3] = cadd(E3, w3o); c[7] = csub(E3, w3o);
}

// ---------- fp32 Stockham passes (generic swz; used by K1/K5) ----------
template<int M>
__device__ __forceinline__ void pass8(const float2* __restrict__ A, float2* __restrict__ B,
                                      int rows, const float2* __restrict__ tw, int tid, int nth) {
    int total = rows << 4;
    for (int idx = tid; idx < total; idx += nth) {
        int r = idx >> 4, t = idx & 15;
        int lo = t & (M - 1), hi = t - lo;
        int base = r << 7;
        float2 a[8], c[8];
        #pragma unroll
        for (int j = 0; j < 8; j++) a[j] = A[base + swz(t + 16 * j)];
        dft8(a, c);
        int p = 8 * hi + lo;
        B[base + swz(p)] = c[0];
        #pragma unroll
        for (int k = 1; k < 8; k++)
            B[base + swz(p + k * M)] = cmul(c[k], tw[(hi * k) & 127]);
    }
}

__device__ __forceinline__ void pass2f(const float2* __restrict__ A, float2* __restrict__ B,
                                       int rows, int tid, int nth) {
    int total = rows << 6;
    for (int idx = tid; idx < total; idx += nth) {
        int r = idx >> 6, t = idx & 63;
        int base = r << 7;
        float2 a0 = A[base + swz(t)];
        float2 a1 = A[base + swz(t + 64)];
        B[base + swz(t)]      = cadd(a0, a1);
        B[base + swz(t + 64)] = csub(a0, a1);
    }
}

__device__ __forceinline__ float2* fft128_r8(float2* A, float2* B, int rows,
                                             const float2* tw, int tid, int nth) {
    pass8<1>(A, B, rows, tw, tid, nth); __syncthreads();
    pass8<8>(B, A, rows, tw, tid, nth); __syncthreads();
    pass2f(A, B, rows, tid, nth);       __syncthreads();
    return B;
}

// ---------- radix-16x8 sparse passes for k_fft_k (swzc addressing) ----------
__device__ __forceinline__ float2 h2f(__half2 v){ return __half22float2(v); }
__device__ __forceinline__ __half2 f2h(float2 v){ return __floats2half2_rn(v.x, v.y); }

// DFT4 combine of twiddled inputs c0..c3 -> d0..d3 (W4 = -i)
#define DFT4_CORE(c0, c1, c2, c3, d0, d1, d2, d3) do {            \
    float2 _e0 = cadd(c0, c2), _e1 = csub(c0, c2);                \
    float2 _o0 = cadd(c1, c3), _o1 = cmulni(csub(c1, c3));        \
    d0 = cadd(_e0, _o0); d1 = cadd(_e1, _o1);                     \
    d2 = csub(_e0, _o0); d3 = csub(_e1, _o1);                     \
} while (0)

// radix-16 first pass (M=1), 4-sparse input (only w<=31 nonzero).
// B[16t+k] = (sum_{j<4} A[t+8j] W16^{jk}) * W128^{t k}
// fp32 version (row phase)
__device__ __forceinline__ void pass16f_sp4(const float2* __restrict__ A, float2* __restrict__ B,
                                            int rows, const float2* __restrict__ tw, int tid, int nth) {
    int total = rows << 3;
    for (int idx = tid; idx < total; idx += nth) {
        int r = idx >> 3, t = idx & 7;
        int base = r << 7;
        float2 b0 = A[base + swzc(r, t)];
        float2 b1 = A[base + swzc(r, t + 8)];
        float2 b2 = A[base + swzc(r, t + 16)];
        float2 b3 = A[base + swzc(r, t + 24)];
        #pragma unroll
        for (int m = 0; m < 4; m++) {
            float2 c1 = cmul(b1, tw[(8  * m) & 127]);
            float2 c2 = cmul(b2, tw[(16 * m) & 127]);
            float2 c3 = cmul(b3, tw[(24 * m) & 127]);
            float2 d0, d1, d2, d3;
            DFT4_CORE(b0, c1, c2, c3, d0, d1, d2, d3);
            B[base + swzc(r, 16*t + m)]      = cmul(d0, tw[(t * (m))      & 127]);
            B[base + swzc(r, 16*t + m + 4)]  = cmul(d1, tw[(t * (m + 4))  & 127]);
            B[base + swzc(r, 16*t + m + 8)]  = cmul(d2, tw[(t * (m + 8))  & 127]);
            B[base + swzc(r, 16*t + m + 12)] = cmul(d3, tw[(t * (m + 12)) & 127]);
        }
    }
}

// fp16-storage version (col phase)
__device__ __forceinline__ void pass16h_sp4(const __half2* __restrict__ A, __half2* __restrict__ B,
                                            int rows, const float2* __restrict__ tw, int tid, int nth) {
    int total = rows << 3;
    for (int idx = tid; idx < total; idx += nth) {
        int r = idx >> 3, t = idx & 7;
        int base = r << 7;
        float2 b0 = h2f(A[base + swzc(r, t)]);
        float2 b1 = h2f(A[base + swzc(r, t + 8)]);
        float2 b2 = h2f(A[base + swzc(r, t + 16)]);
        float2 b3 = h2f(A[base + swzc(r, t + 24)]);
        #pragma unroll
        for (int m = 0; m < 4; m++) {
            float2 c1 = cmul(b1, tw[(8  * m) & 127]);
            float2 c2 = cmul(b2, tw[(16 * m) & 127]);
            float2 c3 = cmul(b3, tw[(24 * m) & 127]);
            float2 d0, d1, d2, d3;
            DFT4_CORE(b0, c1, c2, c3, d0, d1, d2, d3);
            B[base + swzc(r, 16*t + m)]      = f2h(cmul(d0, tw[(t * (m))      & 127]));
            B[base + swzc(r, 16*t + m + 4)]  = f2h(cmul(d1, tw[(t * (m + 4))  & 127]));
            B[base + swzc(r, 16*t + m + 8)]  = f2h(cmul(d2, tw[(t * (m + 8))  & 127]));
            B[base + swzc(r, 16*t + m + 12)] = f2h(cmul(d3, tw[(t * (m + 12)) & 127]));
        }
    }
}

// final radix-8 pass (M=16), hi==0 -> no twiddle. fp32
__device__ __forceinline__ void pass8f_nt(const float2* __restrict__ A, float2* __restrict__ B,
                                          int rows, int tid, int nth) {
    int total = rows << 4;
    for (int idx = tid; idx < total; idx += nth) {
        int r = idx >> 4, t = idx & 15;
        int base = r << 7;
        float2 a[8], c[8];
        #pragma unroll
        for (int j = 0; j < 8; j++) a[j] = A[base + swzc(r, t + 16 * j)];
        dft8(a, c);
        #pragma unroll
        for (int k = 0; k < 8; k++)
            B[base + swzc(r, t + 16 * k)] = c[k];
    }
}

// final radix-8 pass (M=16), fp16 storage
__device__ __forceinline__ void pass8h_nt(const __half2* __restrict__ A, __half2* __restrict__ B,
                                          int rows, int tid, int nth) {
    int total = rows << 4;
    for (int idx = tid; idx < total; idx += nth) {
        int r = idx >> 4, t = idx & 15;
        int base = r << 7;
        float2 a[8], c[8];
        #pragma unroll
        for (int j = 0; j < 8; j++) a[j] = h2f(A[base + swzc(r, t + 16 * j)]);
        dft8(a, c);
        #pragma unroll
        for (int k = 0; k < 8; k++)
            B[base + swzc(r, t + 16 * k)] = f2h(c[k]);
    }
}

// ---------------- K1: 2D rFFT of x -> g_xf[bc][bin] ----------------
__global__ void __launch_bounds__(512) k_fft_x(const float* __restrict__ x) {
    extern __shared__ float2 sm[];
    float2* tw = sm;
    float2* bufA = sm + 128;
    float2* bufB = bufA + NBIN;
    int tid = threadIdx.x, nth = blockDim.x;
    int bc = blockIdx.x;

    make_twiddles(tw, tid);
    const float* img = x + (size_t)bc * HH * WW;
    for (int idx = tid; idx < 64 * 128; idx += nth) {
        int r = idx >> 7, n = idx & 127;
        bufA[(r << 7) + swz(n)] = make_float2(img[(2 * r) * WW + n],
                                              img[(2 * r + 1) * WW + n]);
    }
    __syncthreads();
    float2* P = fft128_r8(bufA, bufB, 64, tw, tid, nth);
    float2* S = bufA;
    for (int idx = tid; idx < 64 * NF; idx += nth) {
        int r = idx / NF, k = idx - r * NF;
        float2 Zk = P[(r << 7) + swz(k)];
        float2 Zn = P[(r << 7) + swz((128 - k) & 127)];
        float2 Ar = make_float2(0.5f * (Zk.x + Zn.x), 0.5f * (Zk.y - Zn.y));
        float2 Br = make_float2(0.5f * (Zk.y + Zn.y), 0.5f * (Zn.x - Zk.x));
        S[(k << 7) + swz(2 * r)]     = Ar;
        S[(k << 7) + swz(2 * r + 1)] = Br;
    }
    __syncthreads();
    float2* Ff = fft128_r8(bufA, bufB, NF, tw, tid, nth);
    float2* ob = g_xf + (size_t)bc * NBIN;
    for (int bin = tid; bin < NBIN; bin += nth) {
        int h = bin & 127;
        ob[bin] = Ff[(bin - h) + swz(h)];    // bin = k*128+h ; (k<<7) = bin-h
    }
}

// ---------------- K2: 2D rFFT of filters (plain, fp16) -> g_kfn[c*F+f][bin] ----------------
// radix-16x8, sparse-4 first passes, swzc addressing.
// smem: tw(1KB) | CA half2[NBIN] | CB half2[NBIN]; RA/RB (fp32) aliased inside CB.
#define SMEM_K2 (1024 + 2 * NBIN * 4)    // 67,584 B
__global__ void __launch_bounds__(512, 2) k_fft_k(const float* __restrict__ filt) {
    extern __shared__ char smk[];
    float2*  tw = (float2*)smk;
    __half2* CA = (__half2*)(smk + 1024);
    __half2* CB = (__half2*)(smk + 1024 + NBIN * 4);
    float2*  RA = (float2*)CB;                              // 16 KB
    float2*  RB = (float2*)(smk + 1024 + NBIN * 4 + 16384); // 16 KB (inside CB region)
    int tid = threadIdx.x, nth = blockDim.x;
    int fc = blockIdx.x;   // f*C + c (natural input order)
    int f = fc >> 7, c = fc & 127;

    make_twiddles(tw, tid);
    for (int idx = tid; idx < 16 * 128; idx += nth)
        RA[idx] = make_float2(0.f, 0.f);
    __syncthreads();
    const float* kimg = filt + (size_t)fc * KHH * KWW;
    for (int idx = tid; idx < KHH * KWW; idx += nth) {
        int i = idx / KWW, j = idx - i * KWW;
        float v = kimg[idx];
        int r = i >> 1;
        if (i & 1) RA[(r << 7) + swzc(r, j)].y = v;
        else       RA[(r << 7) + swzc(r, j)].x = v;
    }
    __syncthreads();
    // row FFT (16 packed rows), sparse-4 (cols 0..30 nonzero): RA -> RB -> RA
    pass16f_sp4(RA, RB, 16, tw, tid, nth); __syncthreads();
    pass8f_nt(RB, RA, 16, tid, nth);       __syncthreads();
    // unpack rfft rows -> CA[k][h] (h < 32 only; those are all the col-FFT inputs)
    for (int idx = tid; idx < 16 * NF; idx += nth) {
        int r = idx / NF, k = idx - r * NF;
        float2 Zk = RA[(r << 7) + swzc(r, k)];
        float2 Zn = RA[(r << 7) + swzc(r, (128 - k) & 127)];
        float2 Ar = make_float2(0.5f * (Zk.x + Zn.x), 0.5f * (Zk.y - Zn.y));
        float2 Br = make_float2(0.5f * (Zk.y + Zn.y), 0.5f * (Zn.x - Zk.x));
        CA[(k << 7) + swzc(k, 2 * r)]     = f2h(Ar);
        CA[(k << 7) + swzc(k, 2 * r + 1)] = f2h(Br);
    }
    __syncthreads();
    // column FFT (65 rows), sparse-4 (h 0..31 nonzero): CA -> CB -> CA
    pass16h_sp4(CA, CB, NF, tw, tid, nth); __syncthreads();
    pass8h_nt(CB, CA, NF, tid, nth);       __syncthreads();
    __half2* ob = g_kfn + (size_t)(c * F + f) * NBIN;   // row = c*F+f for [bin][c][f] layout
    for (int bin = tid; bin < NBIN; bin += nth) {
        int h = bin & 127;
        ob[bin] = CA[(bin - h) + swzc(bin >> 7, h)];
    }
}

// ---------------- K3: transpose kf [cf][bin] -> [bin][cf] (4B elems) ----------------
__global__ void __launch_bounds__(256) k_transpose() {
    __shared__ unsigned int t[32][33];
    const unsigned int* src = (const unsigned int*)g_kfn;
    unsigned int* dst = (unsigned int*)g_kft;
    int x0 = blockIdx.x * 32;   // bin
    int y0 = blockIdx.y * 32;   // cf
    for (int i = threadIdx.y; i < 32; i += 8)
        t[i][threadIdx.x] = src[(size_t)(y0 + i) * NBIN + x0 + threadIdx.x];
    __syncthreads();
    for (int i = threadIdx.y; i < 32; i += 8)
        dst[(size_t)(x0 + i) * FC + y0 + threadIdx.x] = t[threadIdx.x][i];
}

// ---------------- K3x: transpose xf [bc][bin] -> [bin][bc] (8B elems) ----------------
__global__ void __launch_bounds__(256) k_transpose_x() {
    __shared__ float2 t[32][33];
    int x0 = blockIdx.x * 32;   // bin
    int y0 = blockIdx.y * 32;   // bc
    for (int i = threadIdx.y; i < 32; i += 8)
        t[i][threadIdx.x] = g_xf[(size_t)(y0 + i) * NBIN + x0 + threadIdx.x];
    __syncthreads();
    for (int i = threadIdx.y; i < 32; i += 8)
        g_xft[(size_t)(x0 + i) * BC + y0 + threadIdx.x] = t[threadIdx.x][i];
}

// ---------------- K3o: transpose of [bin][bf] -> g_xf (reused) [bf][bin] ----------------
__global__ void __launch_bounds__(256) k_transpose_of() {
    __shared__ float2 t[32][33];
    int b0 = blockIdx.x * 32;   // bin
    int f0 = blockIdx.y * 32;   // bf
    for (int i = threadIdx.y; i < 32; i += 8)
        t[i][threadIdx.x] = g_of[(size_t)(b0 + i) * BC + f0 + threadIdx.x];
    __syncthreads();
    for (int i = threadIdx.y; i < 32; i += 8)
        g_xf[(size_t)(f0 + i) * NBIN + b0 + threadIdx.x] = t[threadIdx.x][i];
}

// ---------------- K4: per-bin complex GEMM via f32x2, cp.async-staged kf ----------------
// thread tile 4f x 4b.  f = 4*lane + j,  b = 4*wid + i.
// kf layout [bin][c][f] fp16 (p,q);  D = X * conj(K):
//   acc += (Xr,Xi) * (p,p)  +  (Xi,-Xr) * (q,q)   -> (Xr*p + Xi*q, Xi*p - Xr*q) ✓
#define CH 16                         // c's per stage
#define K4_XS_BYTES (BC * 16)         // 32KB  float4 (Xr, Xi, Xi, -Xr)
#define K4_KS_BYTES (2 * CH * 512)    // 16KB  double-buffered kf stages
#define SMEM_K4 (K4_XS_BYTES + K4_KS_BYTES)

__global__ void __launch_bounds__(128, 4) k_gemm_fix() {
    extern __shared__ char s4[];
    float4* xs = (float4*)s4;                 // (Xr, Xi, Xi, -Xr)
    uint4*  ks = (uint4*)(s4 + K4_XS_BYTES);
    uint32_t ksb = smem_u32(ks);
    int tid = threadIdx.x, lane = tid & 31, wid = tid >> 5;
    int bin = blockIdx.x;

    const float2* gX = g_xft + (size_t)bin * BC;
    #pragma unroll
    for (int k = 0; k < 16; k++) {
        int i = k * 128 + tid;
        float2 v = gX[i];
        xs[i] = make_float4(v.x, v.y, v.y, -v.x);
    }
    const uint4* gK = (const uint4*)(g_kft + (size_t)bin * FC);   // 32 uint4 per c
    #pragma unroll
    for (int s = 0; s < 2; s++) {
        #pragma unroll
        for (int k = 0; k < 4; k++) {
            int m = k * 128 + tid;
            cp16(ksb + (s * 512 + m) * 16, gK + s * 512 + m);
        }
        asm volatile("cp.async.commit_group;");
    }
    __syncthreads();

    int b0 = wid * 4;
    unsigned long long acc[16];
    #pragma unroll
    for (int i = 0; i < 16; i++) acc[i] = 0ULL;

    #pragma unroll 1
    for (int blk = 0; blk < 8; blk++) {
        if (blk < 7) asm volatile("cp.async.wait_group 1;");
        else         asm volatile("cp.async.wait_group 0;");
        __syncthreads();
        const uint4* kb = ks + (blk & 1) * 512;
        #pragma unroll
        for (int cc = 0; cc < CH; cc++) {
            int c = blk * CH + cc;
            uint4 kq = kb[cc * 32 + lane];          // 4 half2: kf for f=4*lane..4*lane+3
            unsigned long long x1[4], x2[4];
            #pragma unroll
            for (int i = 0; i < 4; i++) {
                float4 xv = xs[(b0 + i) * C + c];   // broadcast LDS
                asm("mov.b64 %0, {%1,%2};" : "=l"(x1[i]) : "f"(xv.x), "f"(xv.y));  // (Xr, Xi)
                asm("mov.b64 %0, {%1,%2};" : "=l"(x2[i]) : "f"(xv.z), "f"(xv.w));  // (Xi, -Xr)
            }
            uint32_t kw[4] = {kq.x, kq.y, kq.z, kq.w};
            #pragma unroll
            for (int j = 0; j < 4; j++) {
                float2 kv = __half22float2(*reinterpret_cast<__half2*>(&kw[j]));   // (p, q)
                unsigned long long Kp, Kq;
                asm("mov.b64 %0, {%1,%2};" : "=l"(Kp) : "f"(kv.x), "f"(kv.x));     // (p, p)
                asm("mov.b64 %0, {%1,%2};" : "=l"(Kq) : "f"(kv.y), "f"(kv.y));     // (q, q)
                #pragma unroll
                for (int i = 0; i < 4; i++) {
                    asm("fma.rn.f32x2 %0, %1, %2, %0;" : "+l"(acc[i * 4 + j]) : "l"(x1[i]), "l"(Kp));
                    asm("fma.rn.f32x2 %0, %1, %2, %0;" : "+l"(acc[i * 4 + j]) : "l"(x2[i]), "l"(Kq));
                }
            }
        }
        __syncthreads();
        if (blk < 6) {
            #pragma unroll
            for (int k = 0; k < 4; k++) {
                int m = k * 128 + tid;
                cp16(ksb + ((blk & 1) * 512 + m) * 16, gK + (blk + 2) * 512 + m);
            }
        }
        asm volatile("cp.async.commit_group;");
    }

    float2* ob = g_of + (size_t)bin * BC;
    #pragma unroll
    for (int i = 0; i < 4; i++) {
        float2 v[4];
        #pragma unroll
        for (int j = 0; j < 4; j++)
            asm("mov.b64 {%0,%1}, %2;" : "=f"(v[j].x), "=f"(v[j].y) : "l"(acc[i * 4 + j]));
        float4* dst = (float4*)&ob[(b0 + i) * F + 4 * lane];
        dst[0] = make_float4(v[0].x, v[0].y, v[1].x, v[1].y);
        dst[1] = make_float4(v[2].x, v[2].y, v[3].x, v[3].y);
    }
}

// ---------------- K5: 2D irFFT + slice + bias (reads of^T from g_xf) ----------------
__global__ void __launch_bounds__(512) k_ifft(float* __restrict__ out,
                                              const float* __restrict__ bias) {
    extern __shared__ float2 sm[];
    float2* tw = sm;
    float2* bufA = sm + 128;
    float2* bufB = bufA + NBIN;
    int tid = threadIdx.x, nth = blockDim.x;
    int bf = blockIdx.x;
    int f  = bf & 127;

    make_twiddles(tw, tid);
    const float2* src = g_xf + (size_t)bf * NBIN;    // of^T row, coalesced
    for (int bin = tid; bin < NBIN; bin += nth) {
        float2 v = src[bin];
        int h = bin & 127;
        bufA[(bin - h) + swz(h)] = make_float2(v.x, -v.y);
    }
    __syncthreads();
    float2* R = fft128_r8(bufA, bufB, NF, tw, tid, nth);
    float2* T = bufA;
    for (int idx = tid; idx < 64 * 128; idx += nth) {
        int r = idx >> 7, k = idx & 127;
        float2 val;
        if (k <= 64) {
            float2 a = R[(k << 7) + swz(2 * r)];
            float2 b = R[(k << 7) + swz(2 * r + 1)];
            val = make_float2(a.x + b.y, a.y - b.x);
        } else {
            int kk = 128 - k;
            float2 a = R[(kk << 7) + swz(2 * r)];
            float2 b = R[(kk << 7) + swz(2 * r + 1)];
            val = make_float2(a.x - b.y, -a.y - b.x);
        }
        T[(r << 7) + swz(k)] = val;
    }
    __syncthreads();
    float2* Y = fft128_r8(bufA, bufB, 64, tw, tid, nth);
    const float inv = 1.0f / 16384.0f;
    float bv = bias[f];
    float* ob = out + (size_t)bf * OH * OW;
    for (int idx = tid; idx < OH * OW; idx += nth) {
        int oh = idx / OW, ow = idx - oh * OW;
        float2 y = Y[((oh >> 1) << 7) + swz(ow)];
        float v = (oh & 1) ? -y.y : y.x;
        ob[idx] = v * inv + bv;
    }
}

// ---------------- launch ----------------
extern "C" void kernel_launch(void* const* d_in, const int* in_sizes, int n_in,
                              void* d_out, int out_size) {
    const float* x    = (const float*)d_in[0];
    const float* filt = (const float*)d_in[1];
    const float* bias = (const float*)d_in[2];
    float* out = (float*)d_out;

    int smFFT = (128 + 2 * NBIN) * (int)sizeof(float2);   // 134,144 B
    cudaFuncSetAttribute(k_fft_x,    cudaFuncAttributeMaxDynamicSharedMemorySize, smFFT);
    cudaFuncSetAttribute(k_fft_k,    cudaFuncAttributeMaxDynamicSharedMemorySize, SMEM_K2);
    cudaFuncSetAttribute(k_ifft,     cudaFuncAttributeMaxDynamicSharedMemorySize, smFFT);
    cudaFuncSetAttribute(k_gemm_fix, cudaFuncAttributeMaxDynamicSharedMemorySize, SMEM_K4);

    k_fft_x<<<BC, 512, smFFT>>>(x);
    k_fft_k<<<FC, 512, SMEM_K2>>>(filt);
    k_transpose<<<dim3(NBIN / 32, FC / 32), dim3(32, 8)>>>();
    k_transpose_x<<<dim3(NBIN / 32, BC / 32), dim3(32, 8)>>>();
    k_gemm_fix<<<NBIN, 128, SMEM_K4>>>();
    k_transpose_of<<<dim3(NBIN / 32, BC / 32), dim3(32, 8)>>>();
    k_ifft<<<BC, 512, smFFT>>>(out, bias);
}